// round 5
// baseline (speedup 1.0000x reference)
#include <cuda_runtime.h>
#include <math.h>

#define NMAX 100000
#define EMAX 1600000
#define H 64
#define ED 32
#define NH 4
#define TOPK 10
#define MAXD 96
#define KK 10

typedef unsigned long long u64;

// ---- packed fp32x2 helpers (sm_103a FFMA2 pipe) -----------------------------
__device__ __forceinline__ u64 pk2(float lo, float hi) {
    u64 d; asm("mov.b64 %0, {%1, %2};" : "=l"(d) : "f"(lo), "f"(hi)); return d;
}
__device__ __forceinline__ void upk2(u64 v, float &lo, float &hi) {
    asm("mov.b64 {%0, %1}, %2;" : "=f"(lo), "=f"(hi) : "l"(v));
}
__device__ __forceinline__ u64 ffma2(u64 a, u64 b, u64 c) {
    u64 d; asm("fma.rn.f32x2 %0, %1, %2, %3;" : "=l"(d) : "l"(a), "l"(b), "l"(c)); return d;
}
__device__ __forceinline__ u64 fadd2(u64 a, u64 b) {
    u64 d; asm("add.rn.f32x2 %0, %1, %2;" : "=l"(d) : "l"(a), "l"(b)); return d;
}

// scratch (static device globals -- no allocation)
__device__ float g_hW[NMAX * H];       // 25.6 MB
__device__ float g_s1[NMAX * NH];
__device__ float g_s2[NMAX * NH];
__device__ float g_score[EMAX];
__device__ int   g_deg[NMAX];
__device__ int   g_start[NMAX];
__device__ int   g_cursor[NMAX];
__device__ int   g_csr[EMAX];
__device__ int   g_bsum[64];

__global__ void k_zero_deg(int n) {
    int i = blockIdx.x * blockDim.x + threadIdx.x;
    if (i < n) g_deg[i] = 0;
}

__global__ void k_count(const int* __restrict__ col, int e_cnt) {
    int i = blockIdx.x * blockDim.x + threadIdx.x;
    if (i < e_cnt) atomicAdd(&g_deg[col[i]], 1);
}

// ---------------------------------------------------------------------------
// per-node precompute: hW = h @ whW + whb (packed f32x2, weights in shared
// as (lane, lane+32) pairs), s1/s2 attn projections.
// ---------------------------------------------------------------------------
__global__ void __launch_bounds__(256)
k_node_linear(const float* __restrict__ h,
              const float* __restrict__ whW,
              const float* __restrict__ whb,
              const float* __restrict__ attn_w,
              int n) {
    __shared__ u64   s_w2[H][32];        // 16 KB packed weight pairs
    __shared__ float s_aw[2 * H * NH];   // 2 KB
    __shared__ u64   s_h2[8][H];         // 4 KB duplicated h pairs per warp
    int tid = threadIdx.x;
    int lane = tid & 31, wl = tid >> 5;
    for (int i = tid; i < H * 32; i += blockDim.x) {
        int k = i >> 5, l = i & 31;
        s_w2[k][l] = pk2(whW[k * H + l], whW[k * H + 32 + l]);
    }
    for (int i = tid; i < 2 * H * NH; i += blockDim.x) s_aw[i] = attn_w[i];
    u64 bias2 = pk2(whb[lane], whb[32 + lane]);
    __syncthreads();

    int warpG = (blockIdx.x * blockDim.x + tid) >> 5;
    int nwarps = (gridDim.x * blockDim.x) >> 5;

    for (int node = warpG; node < n; node += nwarps) {
        float h0 = h[(size_t)node * H + lane];
        float h1 = h[(size_t)node * H + 32 + lane];
        s_h2[wl][lane]      = pk2(h0, h0);
        s_h2[wl][32 + lane] = pk2(h1, h1);
        __syncwarp();
        u64 acc = bias2;
        #pragma unroll
        for (int k = 0; k < H; k += 2) {
            ulonglong2 hp = *reinterpret_cast<const ulonglong2*>(&s_h2[wl][k]);
            acc = ffma2(hp.x, s_w2[k][lane], acc);
            acc = ffma2(hp.y, s_w2[k + 1][lane], acc);
        }
        float a0, a1; upk2(acc, a0, a1);
        g_hW[(size_t)node * H + lane]      = a0;
        g_hW[(size_t)node * H + 32 + lane] = a1;
        if (lane < 8) {
            int which = lane >> 2, head = lane & 3;
            const float* aw = s_aw + which * H * NH;
            const float* hp = h + (size_t)node * H;
            float s = 0.f;
            #pragma unroll
            for (int k = 0; k < H; k++) s += hp[k] * aw[k * NH + head];
            if (which == 0) g_s1[node * NH + head] = s;
            else            g_s2[node * NH + head] = s;
        }
        __syncwarp();
    }
}

// ---------------------------------------------------------------------------
// multi-block scan of g_deg -> g_start/g_cursor. 2048 elems / block.
// ---------------------------------------------------------------------------
__global__ void __launch_bounds__(256)
k_scan_part(int n) {
    __shared__ int s_wsum[8];
    int b = blockIdx.x, t = threadIdx.x;
    int base = b * 2048 + t * 8;
    int v[8];
    #pragma unroll
    for (int j = 0; j < 8; j++) v[j] = (base + j < n) ? g_deg[base + j] : 0;
    int tsum = 0;
    #pragma unroll
    for (int j = 0; j < 8; j++) { int x = v[j]; v[j] = tsum; tsum += x; }
    int lane = t & 31, wid = t >> 5;
    int x = tsum;
    #pragma unroll
    for (int off = 1; off < 32; off <<= 1) {
        int y = __shfl_up_sync(0xffffffffu, x, off);
        if (lane >= off) x += y;
    }
    if (lane == 31) s_wsum[wid] = x;
    __syncthreads();
    if (t == 0) {
        int a = 0;
        #pragma unroll
        for (int w = 0; w < 8; w++) { int tt = s_wsum[w]; s_wsum[w] = a; a += tt; }
        g_bsum[b] = a;
    }
    __syncthreads();
    int excl = s_wsum[wid] + (x - tsum);
    #pragma unroll
    for (int j = 0; j < 8; j++)
        if (base + j < n) g_start[base + j] = excl + v[j];
}

__global__ void k_scan_top(int nb) {
    if (threadIdx.x == 0 && blockIdx.x == 0) {
        int a = 0;
        for (int i = 0; i < nb; i++) { int t = g_bsum[i]; g_bsum[i] = a; a += t; }
    }
}

__global__ void k_scan_add(int n) {
    int i = blockIdx.x * blockDim.x + threadIdx.x;
    if (i < n) {
        int s = g_start[i] + g_bsum[i >> 11];
        g_start[i] = s;
        g_cursor[i] = s;
    }
}

// ---------------------------------------------------------------------------
// fused per-edge attention score + CSR scatter.
// ---------------------------------------------------------------------------
__global__ void __launch_bounds__(256)
k_score_scatter(const int* __restrict__ row,
                const int* __restrict__ col,
                const float* __restrict__ edge_attr,
                const float* __restrict__ attn_w,
                int e_cnt) {
    __shared__ float s_a3[ED * NH];
    int tid = threadIdx.x;
    for (int i = tid; i < ED * NH; i += blockDim.x)
        s_a3[i] = attn_w[2 * H * NH + i];
    __syncthreads();

    int e = blockIdx.x * blockDim.x + tid;
    if (e >= e_cnt) return;
    int r = row[e], c = col[e];
    float4 p1 = reinterpret_cast<const float4*>(g_s1)[r];
    float4 p2 = reinterpret_cast<const float4*>(g_s2)[c];
    const float4* ea4 = reinterpret_cast<const float4*>(edge_attr + (size_t)e * ED);
    float s3[NH] = {0.f, 0.f, 0.f, 0.f};
    #pragma unroll
    for (int q = 0; q < 8; q++) {
        float4 v = ea4[q];
        int k = q * 4;
        #pragma unroll
        for (int hd = 0; hd < NH; hd++) {
            s3[hd] += v.x * s_a3[(k    ) * NH + hd];
            s3[hd] += v.y * s_a3[(k + 1) * NH + hd];
            s3[hd] += v.z * s_a3[(k + 2) * NH + hd];
            s3[hd] += v.w * s_a3[(k + 3) * NH + hd];
        }
    }
    float t0 = p1.x + p2.x + s3[0];
    float t1 = p1.y + p2.y + s3[1];
    float t2 = p1.z + p2.z + s3[2];
    float t3 = p1.w + p2.w + s3[3];
    t0 = (t0 >= 0.f) ? t0 : 0.2f * t0;
    t1 = (t1 >= 0.f) ? t1 : 0.2f * t1;
    t2 = (t2 >= 0.f) ? t2 : 0.2f * t2;
    t3 = (t3 >= 0.f) ? t3 : 0.2f * t3;
    g_score[e] = 0.25f * (t0 + t1 + t2 + t3);
    int p = atomicAdd(&g_cursor[c], 1);
    g_csr[p] = e;
}

// ---------------------------------------------------------------------------
// warp-per-node aggregation with packed f32x2 MAC loop.
// ---------------------------------------------------------------------------
__global__ void __launch_bounds__(256)
k_node_agg(const int* __restrict__ row,
           const float* __restrict__ edge_attr,
           const int* __restrict__ labels,
           const float* __restrict__ weW,
           const float* __restrict__ web,
           float* __restrict__ out,
           int n) {
    __shared__ float s_sc[8][MAXD];        // 3 KB
    __shared__ int   s_eid[8][MAXD];       // 3 KB
    __shared__ float s_ka[8][KK];
    __shared__ int   s_ke[8][KK];
    __shared__ u64   s_ea2[8][KK][ED];     // 20 KB duplicated ea pairs
    __shared__ u64   s_hw2[8][KK][32];     // 20 KB (v0,v1) pairs

    int tid = threadIdx.x;
    int lane = tid & 31, wl = tid >> 5;

    // packed weights: wp[k] = (weW[k][lane], weW[k][lane+32])
    u64 wp[ED];
    #pragma unroll
    for (int k = 0; k < ED; k++)
        wp[k] = pk2(weW[k * H + lane], weW[k * H + 32 + lane]);
    u64 bias2 = pk2(web[lane], web[32 + lane]);

    int warpG = (blockIdx.x * blockDim.x + tid) >> 5;
    int nwarps = (gridDim.x * blockDim.x) >> 5;

    for (int node = warpG; node < n; node += nwarps) {
        int d = g_deg[node], st = g_start[node];
        float acc0 = 0.f, acc1 = 0.f, acc2 = 0.f, acc3 = 0.f, acc4 = 0.f, acc5 = 0.f;
        int kk = 0;
        if (d > 0 && d <= 32) {
            // -------- register fast path --------
            bool valid = lane < d;
            int   e  = valid ? g_csr[st + lane] : 0x7FFFFFFF;
            float sc = valid ? g_score[e] : 0.f;
            // warp bitonic sort ascending by edge id (payload sc)
            #pragma unroll
            for (int k2 = 2; k2 <= 32; k2 <<= 1) {
                #pragma unroll
                for (int j = k2 >> 1; j > 0; j >>= 1) {
                    int   pe  = __shfl_xor_sync(0xffffffffu, e,  j);
                    float psc = __shfl_xor_sync(0xffffffffu, sc, j);
                    bool keepMin = ((lane & k2) == 0) == ((lane & j) == 0);
                    if ((e < pe) != keepMin) { e = pe; sc = psc; }
                }
            }
            valid = lane < d;
            float mx = valid ? sc : -1e30f;
            #pragma unroll
            for (int off = 16; off; off >>= 1)
                mx = fmaxf(mx, __shfl_xor_sync(0xffffffffu, mx, off));
            float ex = valid ? expf(sc - mx) : 0.f;
            float sum = ex;
            #pragma unroll
            for (int off = 16; off; off >>= 1)
                sum += __shfl_xor_sync(0xffffffffu, sum, off);
            float invden = 1.f / sum;
            int cnt = 0;
            if (d > TOPK) {
                for (int j = 0; j < d; j++) {
                    float scj = __shfl_sync(0xffffffffu, sc, j);
                    int   ej  = __shfl_sync(0xffffffffu, e,  j);
                    cnt += (scj > sc) || (scj == sc && ej < e);
                }
            }
            bool keep = valid && (cnt < TOPK);
            unsigned bal = __ballot_sync(0xffffffffu, keep);
            kk = __popc(bal);
            int pos = __popc(bal & ((1u << lane) - 1u));
            if (keep) {
                s_ka[wl][pos] = ex * invden;
                s_ke[wl][pos] = e;
            }
            __syncwarp();
        } else if (d > 32 && d <= MAXD) {
            // -------- shared path (rare) --------
            for (int i = lane; i < d; i += 32) {
                int e = g_csr[st + i];
                s_eid[wl][i] = e;
                s_sc[wl][i] = g_score[e];
            }
            __syncwarp();
            for (int p = 0; p < d; p++) {
                for (int i = 2 * lane + (p & 1); i + 1 < d; i += 64) {
                    int e0 = s_eid[wl][i], e1 = s_eid[wl][i + 1];
                    if (e0 > e1) {
                        s_eid[wl][i] = e1; s_eid[wl][i + 1] = e0;
                        float tt = s_sc[wl][i];
                        s_sc[wl][i] = s_sc[wl][i + 1];
                        s_sc[wl][i + 1] = tt;
                    }
                }
                __syncwarp();
            }
            float mx = -1e30f;
            for (int i = lane; i < d; i += 32) mx = fmaxf(mx, s_sc[wl][i]);
            #pragma unroll
            for (int off = 16; off; off >>= 1)
                mx = fmaxf(mx, __shfl_xor_sync(0xffffffffu, mx, off));
            float sum = 0.f;
            for (int i = lane; i < d; i += 32) sum += expf(s_sc[wl][i] - mx);
            #pragma unroll
            for (int off = 16; off; off >>= 1)
                sum += __shfl_xor_sync(0xffffffffu, sum, off);
            float invden = 1.f / sum;
            for (int base = 0; base < d; base += 32) {
                int i = base + lane;
                bool valid = (i < d);
                bool keep = false;
                float a = 0.f;
                if (valid) {
                    float sci = s_sc[wl][i];
                    int ei = s_eid[wl][i];
                    int c = 0;
                    for (int j = 0; j < d; j++) {
                        float scj = s_sc[wl][j];
                        c += (scj > sci) || (scj == sci && s_eid[wl][j] < ei);
                    }
                    keep = (c < TOPK);
                    if (keep) a = expf(sci - mx) * invden;
                }
                unsigned bal = __ballot_sync(0xffffffffu, valid && keep);
                int pos = kk + __popc(bal & ((1u << lane) - 1u));
                if (valid && keep) {
                    s_ka[wl][pos] = a;
                    s_ke[wl][pos] = s_eid[wl][i];
                }
                kk += __popc(bal);
            }
            __syncwarp();
        } else if (d > MAXD) {
            // -------- giant fallback (effectively never) --------
            int lc = labels[node];
            float mx = -1e30f;
            for (int i = lane; i < d; i += 32) mx = fmaxf(mx, g_score[g_csr[st + i]]);
            #pragma unroll
            for (int off = 16; off; off >>= 1)
                mx = fmaxf(mx, __shfl_xor_sync(0xffffffffu, mx, off));
            float sum = 0.f;
            for (int i = lane; i < d; i += 32) sum += expf(g_score[g_csr[st + i]] - mx);
            #pragma unroll
            for (int off = 16; off; off >>= 1)
                sum += __shfl_xor_sync(0xffffffffu, sum, off);
            float invden = 1.f / sum;
            for (int i = 0; i < d; i++) {
                int e = g_csr[st + i];
                float sci = g_score[e];
                int c = 0;
                for (int j = lane; j < d; j += 32) {
                    int ej = g_csr[st + j];
                    float scj = g_score[ej];
                    c += (scj > sci) || (scj == sci && ej < e);
                }
                #pragma unroll
                for (int off = 16; off; off >>= 1)
                    c += __shfl_xor_sync(0xffffffffu, c, off);
                if (c >= TOPK) continue;
                float a = expf(sci - mx) * invden;
                int r = row[e];
                int lr = labels[r];
                int g = (lr < 0 || lc < 0) ? 2 : ((lr == lc) ? 0 : 1);
                float eav = edge_attr[(size_t)e * ED + lane];
                u64 w = bias2;
                #pragma unroll
                for (int k = 0; k < ED; k++) {
                    float b = __shfl_sync(0xffffffffu, eav, k);
                    w = ffma2(pk2(b, b), wp[k], w);
                }
                float w0, w1; upk2(w, w0, w1);
                float m0 = fmaxf(g_hW[(size_t)r * H + lane] + w0, 0.f);
                float m1 = fmaxf(g_hW[(size_t)r * H + 32 + lane] + w1, 0.f);
                if (g == 0)      { acc0 += a * m0; acc1 += a * m1; }
                else if (g == 1) { acc2 += a * m0; acc3 += a * m1; }
                else             { acc4 += a * m0; acc5 += a * m1; }
            }
        }

        if (kk > 0) {
            int lc = labels[node];
            int e_reg = 0, r_reg = 0, g_reg = 2;
            float a_reg = 0.f;
            if (lane < kk) {
                e_reg = s_ke[wl][lane];
                a_reg = s_ka[wl][lane];
                r_reg = row[e_reg];
                int lr = labels[r_reg];
                g_reg = (lr < 0 || lc < 0) ? 2 : ((lr == lc) ? 0 : 1);
            }
            // batch prefetch (independent loads -> high MLP)
            for (int i = 0; i < kk; i++) {
                int e_i = __shfl_sync(0xffffffffu, e_reg, i);
                int r_i = __shfl_sync(0xffffffffu, r_reg, i);
                float ev = edge_attr[(size_t)e_i * ED + lane];
                s_ea2[wl][i][lane] = pk2(ev, ev);
                float v0 = g_hW[(size_t)r_i * H + lane];
                float v1 = g_hW[(size_t)r_i * H + 32 + lane];
                s_hw2[wl][i][lane] = pk2(v0, v1);
            }
            __syncwarp();
            // MAC loop: LDS.128 broadcast pairs + packed FFMA2
            for (int i = 0; i < kk; i++) {
                float a = __shfl_sync(0xffffffffu, a_reg, i);
                int g = __shfl_sync(0xffffffffu, g_reg, i);
                const u64* ep = s_ea2[wl][i];
                u64 w = bias2;
                #pragma unroll
                for (int k = 0; k < ED; k += 2) {
                    ulonglong2 p = *reinterpret_cast<const ulonglong2*>(ep + k);
                    w = ffma2(p.x, wp[k], w);
                    w = ffma2(p.y, wp[k + 1], w);
                }
                w = fadd2(w, s_hw2[wl][i][lane]);
                float m0, m1; upk2(w, m0, m1);
                m0 = fmaxf(m0, 0.f);
                m1 = fmaxf(m1, 0.f);
                if (g == 0)      { acc0 += a * m0; acc1 += a * m1; }
                else if (g == 1) { acc2 += a * m0; acc3 += a * m1; }
                else             { acc4 += a * m0; acc5 += a * m1; }
            }
        }

        size_t ob = (size_t)node * (3 * H);
        out[ob + lane]              = acc0;
        out[ob + 32 + lane]         = acc1;
        out[ob + H + lane]          = acc2;
        out[ob + H + 32 + lane]     = acc3;
        out[ob + 2 * H + lane]      = acc4;
        out[ob + 2 * H + 32 + lane] = acc5;
    }
}

// ---------------------------------------------------------------------------
extern "C" void kernel_launch(void* const* d_in, const int* in_sizes, int n_in,
                              void* d_out, int out_size) {
    const float* h         = (const float*)d_in[0];
    const int*   edge_idx  = (const int*)  d_in[1];
    const float* edge_attr = (const float*)d_in[2];
    const int*   labels    = (const int*)  d_in[3];
    const float* attn_w    = (const float*)d_in[4];
    const float* whW       = (const float*)d_in[5];
    const float* whb       = (const float*)d_in[6];
    const float* weW       = (const float*)d_in[7];
    const float* web       = (const float*)d_in[8];
    float* out = (float*)d_out;

    int n = in_sizes[0] / H;
    int e = in_sizes[1] / 2;
    const int* row = edge_idx;
    const int* col = edge_idx + e;

    int nb = (n + 2047) / 2048;

    k_zero_deg<<<(n + 255) / 256, 256>>>(n);
    k_count<<<(e + 255) / 256, 256>>>(col, e);
    k_node_linear<<<592, 256>>>(h, whW, whb, attn_w, n);
    k_scan_part<<<nb, 256>>>(n);
    k_scan_top<<<1, 32>>>(nb);
    k_scan_add<<<(n + 255) / 256, 256>>>(n);
    k_score_scatter<<<(e + 255) / 256, 256>>>(row, col, edge_attr, attn_w, e);
    k_node_agg<<<592, 256>>>(row, edge_attr, labels, weW, web, out, n);
}

// round 6
// speedup vs baseline: 1.0931x; 1.0931x over previous
#include <cuda_runtime.h>
#include <math.h>

#define NMAX 100000
#define EMAX 1600000
#define H 64
#define ED 32
#define NH 4
#define TOPK 10
#define MAXD 96
#define KK 10

// scratch (static device globals -- zero-initialized at module load)
__device__ float g_hW[NMAX * H];       // 25.6 MB
__device__ float g_s1[NMAX * NH];
__device__ float g_s2[NMAX * NH];
__device__ float g_score[EMAX];
__device__ int   g_deg[NMAX];          // invariant: all-zero at entry of each kernel_launch
__device__ int   g_start[NMAX];
__device__ int   g_cursor[NMAX];
__device__ int   g_csr[EMAX];
__device__ int   g_bsum[64];

__global__ void k_count(const int* __restrict__ col, int e_cnt) {
    int i = blockIdx.x * blockDim.x + threadIdx.x;
    if (i < e_cnt) atomicAdd(&g_deg[col[i]], 1);
}

// ---------------------------------------------------------------------------
// multi-block scan of g_deg -> g_start. 2048 elems / block, totals in g_bsum.
// ---------------------------------------------------------------------------
__global__ void __launch_bounds__(256)
k_scan_part(int n) {
    __shared__ int s_wsum[8];
    int b = blockIdx.x, t = threadIdx.x;
    int base = b * 2048 + t * 8;
    int v[8];
    #pragma unroll
    for (int j = 0; j < 8; j++) v[j] = (base + j < n) ? g_deg[base + j] : 0;
    int tsum = 0;
    #pragma unroll
    for (int j = 0; j < 8; j++) { int x = v[j]; v[j] = tsum; tsum += x; }
    int lane = t & 31, wid = t >> 5;
    int x = tsum;
    #pragma unroll
    for (int off = 1; off < 32; off <<= 1) {
        int y = __shfl_up_sync(0xffffffffu, x, off);
        if (lane >= off) x += y;
    }
    if (lane == 31) s_wsum[wid] = x;
    __syncthreads();
    if (t == 0) {
        int a = 0;
        #pragma unroll
        for (int w = 0; w < 8; w++) { int tt = s_wsum[w]; s_wsum[w] = a; a += tt; }
        g_bsum[b] = a;
    }
    __syncthreads();
    int excl = s_wsum[wid] + (x - tsum);
    #pragma unroll
    for (int j = 0; j < 8; j++)
        if (base + j < n) g_start[base + j] = excl + v[j];
}

// scan_add with fused top-level prefix (each block prefixes g_bsum locally)
__global__ void __launch_bounds__(256)
k_scan_add(int n, int nb) {
    __shared__ int s_pref[64];
    int t = threadIdx.x;
    if (t == 0) {
        int a = 0;
        for (int i = 0; i < nb; i++) { int v = g_bsum[i]; s_pref[i] = a; a += v; }
    }
    __syncthreads();
    int i = blockIdx.x * blockDim.x + t;
    if (i < n) {
        int s = g_start[i] + s_pref[i >> 11];
        g_start[i] = s;
        g_cursor[i] = s;
    }
}

// ---------------------------------------------------------------------------
// per-node precompute: hW = h @ whW + whb, s1/s2 attn projections.
// whW columns register-resident, h broadcast via shfl.
// ---------------------------------------------------------------------------
__global__ void __launch_bounds__(256)
k_node_linear(const float* __restrict__ h,
              const float* __restrict__ whW,
              const float* __restrict__ whb,
              const float* __restrict__ attn_w,
              int n) {
    __shared__ float s_aw[2 * H * NH];
    int tid = threadIdx.x;
    int lane = tid & 31;
    for (int i = tid; i < 2 * H * NH; i += blockDim.x) s_aw[i] = attn_w[i];

    float wlo[H], whi[H];
    #pragma unroll
    for (int k = 0; k < H; k++) {
        wlo[k] = whW[k * H + lane];
        whi[k] = whW[k * H + 32 + lane];
    }
    float blo = whb[lane], bhi = whb[32 + lane];
    __syncthreads();

    int warpG = (blockIdx.x * blockDim.x + tid) >> 5;
    int nwarps = (gridDim.x * blockDim.x) >> 5;

    for (int node = warpG; node < n; node += nwarps) {
        float h0 = h[(size_t)node * H + lane];
        float h1 = h[(size_t)node * H + 32 + lane];
        float a0 = 0.f, a1 = 0.f;
        #pragma unroll
        for (int k = 0; k < 32; k++) {
            float hk = __shfl_sync(0xffffffffu, h0, k);
            a0 += hk * wlo[k];
            a1 += hk * whi[k];
        }
        #pragma unroll
        for (int k = 0; k < 32; k++) {
            float hk = __shfl_sync(0xffffffffu, h1, k);
            a0 += hk * wlo[32 + k];
            a1 += hk * whi[32 + k];
        }
        g_hW[(size_t)node * H + lane]      = a0 + blo;
        g_hW[(size_t)node * H + 32 + lane] = a1 + bhi;
        if (lane < 8) {
            int which = lane >> 2, head = lane & 3;
            const float* aw = s_aw + which * H * NH;
            const float* hp = h + (size_t)node * H;
            float s = 0.f;
            #pragma unroll
            for (int k = 0; k < H; k++) s += hp[k] * aw[k * NH + head];
            if (which == 0) g_s1[node * NH + head] = s;
            else            g_s2[node * NH + head] = s;
        }
    }
}

// ---------------------------------------------------------------------------
// fused per-edge attention score + CSR scatter.
// ---------------------------------------------------------------------------
__global__ void __launch_bounds__(256)
k_score_scatter(const int* __restrict__ row,
                const int* __restrict__ col,
                const float* __restrict__ edge_attr,
                const float* __restrict__ attn_w,
                int e_cnt) {
    __shared__ float s_a3[ED * NH];
    int tid = threadIdx.x;
    for (int i = tid; i < ED * NH; i += blockDim.x)
        s_a3[i] = attn_w[2 * H * NH + i];
    __syncthreads();

    int e = blockIdx.x * blockDim.x + tid;
    if (e >= e_cnt) return;
    int r = row[e], c = col[e];
    float4 p1 = reinterpret_cast<const float4*>(g_s1)[r];
    float4 p2 = reinterpret_cast<const float4*>(g_s2)[c];
    const float4* ea4 = reinterpret_cast<const float4*>(edge_attr + (size_t)e * ED);
    float s3[NH] = {0.f, 0.f, 0.f, 0.f};
    #pragma unroll
    for (int q = 0; q < 8; q++) {
        float4 v = ea4[q];
        int k = q * 4;
        #pragma unroll
        for (int hd = 0; hd < NH; hd++) {
            s3[hd] += v.x * s_a3[(k    ) * NH + hd];
            s3[hd] += v.y * s_a3[(k + 1) * NH + hd];
            s3[hd] += v.z * s_a3[(k + 2) * NH + hd];
            s3[hd] += v.w * s_a3[(k + 3) * NH + hd];
        }
    }
    float t0 = p1.x + p2.x + s3[0];
    float t1 = p1.y + p2.y + s3[1];
    float t2 = p1.z + p2.z + s3[2];
    float t3 = p1.w + p2.w + s3[3];
    t0 = (t0 >= 0.f) ? t0 : 0.2f * t0;
    t1 = (t1 >= 0.f) ? t1 : 0.2f * t1;
    t2 = (t2 >= 0.f) ? t2 : 0.2f * t2;
    t3 = (t3 >= 0.f) ? t3 : 0.2f * t3;
    g_score[e] = 0.25f * (t0 + t1 + t2 + t3);
    int p = atomicAdd(&g_cursor[c], 1);
    g_csr[p] = e;
}

// ---------------------------------------------------------------------------
// warp-per-node aggregation. NO SORT (keep-mask is order-independent; fp32
// summation-order noise ~1e-6 << 1e-3 tolerance).
//  d<=32 : register path.  32<d<=96 : shared path.  d>96 : global fallback.
// Self-cleaning: zeroes g_deg[node] after use.
// ---------------------------------------------------------------------------
__global__ void __launch_bounds__(256)
k_node_agg(const int* __restrict__ row,
           const float* __restrict__ edge_attr,
           const int* __restrict__ labels,
           const float* __restrict__ weW,
           const float* __restrict__ web,
           float* __restrict__ out,
           int n) {
    __shared__ float s_sc[8][MAXD];
    __shared__ int   s_eid[8][MAXD];
    __shared__ float s_ka[8][KK];
    __shared__ int   s_ke[8][KK];
    __shared__ float s_eav[8][KK][32];
    __shared__ float s_hw[8][KK][64];

    int tid = threadIdx.x;
    int lane = tid & 31, wl = tid >> 5;

    float wlo[ED], whi[ED];
    #pragma unroll
    for (int k = 0; k < ED; k++) {
        wlo[k] = weW[k * H + lane];
        whi[k] = weW[k * H + 32 + lane];
    }
    float blo = web[lane], bhi = web[32 + lane];

    int warpG = (blockIdx.x * blockDim.x + tid) >> 5;
    int nwarps = (gridDim.x * blockDim.x) >> 5;

    for (int node = warpG; node < n; node += nwarps) {
        int d = g_deg[node], st = g_start[node];
        float acc0 = 0.f, acc1 = 0.f, acc2 = 0.f, acc3 = 0.f, acc4 = 0.f, acc5 = 0.f;
        int kk = 0;
        if (d > 0 && d <= 32) {
            // -------- register fast path (no sort) --------
            bool valid = lane < d;
            int   e  = valid ? g_csr[st + lane] : 0x7FFFFFFF;
            float sc = valid ? g_score[e] : -1e30f;
            float mx = sc;
            #pragma unroll
            for (int off = 16; off; off >>= 1)
                mx = fmaxf(mx, __shfl_xor_sync(0xffffffffu, mx, off));
            float ex = valid ? expf(sc - mx) : 0.f;
            float sum = ex;
            #pragma unroll
            for (int off = 16; off; off >>= 1)
                sum += __shfl_xor_sync(0xffffffffu, sum, off);
            float invden = 1.f / sum;
            int cnt = 0;
            if (d > TOPK) {
                for (int j = 0; j < d; j++) {
                    float scj = __shfl_sync(0xffffffffu, sc, j);
                    int   ej  = __shfl_sync(0xffffffffu, e,  j);
                    cnt += (scj > sc) || (scj == sc && ej < e);
                }
            }
            bool keep = valid && (cnt < TOPK);
            unsigned bal = __ballot_sync(0xffffffffu, keep);
            kk = __popc(bal);
            int pos = __popc(bal & ((1u << lane) - 1u));
            if (keep) {
                s_ka[wl][pos] = ex * invden;
                s_ke[wl][pos] = e;
            }
            __syncwarp();
        } else if (d > 32 && d <= MAXD) {
            // -------- shared path (rare, no sort) --------
            for (int i = lane; i < d; i += 32) {
                int e = g_csr[st + i];
                s_eid[wl][i] = e;
                s_sc[wl][i] = g_score[e];
            }
            __syncwarp();
            float mx = -1e30f;
            for (int i = lane; i < d; i += 32) mx = fmaxf(mx, s_sc[wl][i]);
            #pragma unroll
            for (int off = 16; off; off >>= 1)
                mx = fmaxf(mx, __shfl_xor_sync(0xffffffffu, mx, off));
            float sum = 0.f;
            for (int i = lane; i < d; i += 32) sum += expf(s_sc[wl][i] - mx);
            #pragma unroll
            for (int off = 16; off; off >>= 1)
                sum += __shfl_xor_sync(0xffffffffu, sum, off);
            float invden = 1.f / sum;
            for (int base = 0; base < d; base += 32) {
                int i = base + lane;
                bool valid = (i < d);
                bool keep = false;
                float a = 0.f;
                if (valid) {
                    float sci = s_sc[wl][i];
                    int ei = s_eid[wl][i];
                    int c = 0;
                    for (int j = 0; j < d; j++) {
                        float scj = s_sc[wl][j];
                        c += (scj > sci) || (scj == sci && s_eid[wl][j] < ei);
                    }
                    keep = (c < TOPK);
                    if (keep) a = expf(sci - mx) * invden;
                }
                unsigned bal = __ballot_sync(0xffffffffu, valid && keep);
                int pos = kk + __popc(bal & ((1u << lane) - 1u));
                if (valid && keep) {
                    s_ka[wl][pos] = a;
                    s_ke[wl][pos] = s_eid[wl][i];
                }
                kk += __popc(bal);
            }
            __syncwarp();
        } else if (d > MAXD) {
            // -------- giant fallback (effectively never) --------
            int lc = labels[node];
            float mx = -1e30f;
            for (int i = lane; i < d; i += 32) mx = fmaxf(mx, g_score[g_csr[st + i]]);
            #pragma unroll
            for (int off = 16; off; off >>= 1)
                mx = fmaxf(mx, __shfl_xor_sync(0xffffffffu, mx, off));
            float sum = 0.f;
            for (int i = lane; i < d; i += 32) sum += expf(g_score[g_csr[st + i]] - mx);
            #pragma unroll
            for (int off = 16; off; off >>= 1)
                sum += __shfl_xor_sync(0xffffffffu, sum, off);
            float invden = 1.f / sum;
            for (int i = 0; i < d; i++) {
                int e = g_csr[st + i];
                float sci = g_score[e];
                int c = 0;
                for (int j = lane; j < d; j += 32) {
                    int ej = g_csr[st + j];
                    float scj = g_score[ej];
                    c += (scj > sci) || (scj == sci && ej < e);
                }
                #pragma unroll
                for (int off = 16; off; off >>= 1)
                    c += __shfl_xor_sync(0xffffffffu, c, off);
                if (c >= TOPK) continue;
                float a = expf(sci - mx) * invden;
                int r = row[e];
                int lr = labels[r];
                int g = (lr < 0 || lc < 0) ? 2 : ((lr == lc) ? 0 : 1);
                float eav = edge_attr[(size_t)e * ED + lane];
                float v0 = g_hW[(size_t)r * H + lane];
                float v1 = g_hW[(size_t)r * H + 32 + lane];
                float w0 = 0.f, w1 = 0.f;
                #pragma unroll
                for (int k = 0; k < ED; k++) {
                    float b = __shfl_sync(0xffffffffu, eav, k);
                    w0 += b * wlo[k];
                    w1 += b * whi[k];
                }
                float m0 = fmaxf(v0 + w0 + blo, 0.f);
                float m1 = fmaxf(v1 + w1 + bhi, 0.f);
                if (g == 0)      { acc0 += a * m0; acc1 += a * m1; }
                else if (g == 1) { acc2 += a * m0; acc3 += a * m1; }
                else             { acc4 += a * m0; acc5 += a * m1; }
            }
        }

        if (kk > 0) {
            int lc = labels[node];
            int e_reg = 0, r_reg = 0, g_reg = 2;
            float a_reg = 0.f;
            if (lane < kk) {
                e_reg = s_ke[wl][lane];
                a_reg = s_ka[wl][lane];
                r_reg = row[e_reg];
                int lr = labels[r_reg];
                g_reg = (lr < 0 || lc < 0) ? 2 : ((lr == lc) ? 0 : 1);
            }
            // batch prefetch (independent loads -> high MLP)
            for (int i = 0; i < kk; i++) {
                int e_i = __shfl_sync(0xffffffffu, e_reg, i);
                int r_i = __shfl_sync(0xffffffffu, r_reg, i);
                s_eav[wl][i][lane]     = edge_attr[(size_t)e_i * ED + lane];
                s_hw[wl][i][lane]      = g_hW[(size_t)r_i * H + lane];
                s_hw[wl][i][32 + lane] = g_hW[(size_t)r_i * H + 32 + lane];
            }
            __syncwarp();
            // MAC loop: broadcast LDS + FFMA
            for (int i = 0; i < kk; i++) {
                float a = __shfl_sync(0xffffffffu, a_reg, i);
                int g = __shfl_sync(0xffffffffu, g_reg, i);
                float w0 = 0.f, w1 = 0.f;
                #pragma unroll
                for (int k = 0; k < ED; k++) {
                    float bv = s_eav[wl][i][k];
                    w0 += bv * wlo[k];
                    w1 += bv * whi[k];
                }
                float m0 = fmaxf(s_hw[wl][i][lane] + w0 + blo, 0.f);
                float m1 = fmaxf(s_hw[wl][i][32 + lane] + w1 + bhi, 0.f);
                if (g == 0)      { acc0 += a * m0; acc1 += a * m1; }
                else if (g == 1) { acc2 += a * m0; acc3 += a * m1; }
                else             { acc4 += a * m0; acc5 += a * m1; }
            }
        }

        // self-clean for next graph replay (module-load state is all-zero)
        g_deg[node] = 0;

        size_t ob = (size_t)node * (3 * H);
        out[ob + lane]              = acc0;
        out[ob + 32 + lane]         = acc1;
        out[ob + H + lane]          = acc2;
        out[ob + H + 32 + lane]     = acc3;
        out[ob + 2 * H + lane]      = acc4;
        out[ob + 2 * H + 32 + lane] = acc5;
    }
}

// ---------------------------------------------------------------------------
extern "C" void kernel_launch(void* const* d_in, const int* in_sizes, int n_in,
                              void* d_out, int out_size) {
    const float* h         = (const float*)d_in[0];
    const int*   edge_idx  = (const int*)  d_in[1];
    const float* edge_attr = (const float*)d_in[2];
    const int*   labels    = (const int*)  d_in[3];
    const float* attn_w    = (const float*)d_in[4];
    const float* whW       = (const float*)d_in[5];
    const float* whb       = (const float*)d_in[6];
    const float* weW       = (const float*)d_in[7];
    const float* web       = (const float*)d_in[8];
    float* out = (float*)d_out;

    int n = in_sizes[0] / H;
    int e = in_sizes[1] / 2;
    const int* row = edge_idx;
    const int* col = edge_idx + e;

    int nb = (n + 2047) / 2048;

    k_count<<<(e + 255) / 256, 256>>>(col, e);
    k_scan_part<<<nb, 256>>>(n);
    k_scan_add<<<(n + 255) / 256, 256>>>(n, nb);
    k_node_linear<<<592, 256>>>(h, whW, whb, attn_w, n);   // profiled slot
    k_score_scatter<<<(e + 255) / 256, 256>>>(row, col, edge_attr, attn_w, e);
    k_node_agg<<<592, 256>>>(row, edge_attr, labels, weW, web, out, n);
}

// round 7
// speedup vs baseline: 1.2423x; 1.1365x over previous
#include <cuda_runtime.h>
#include <math.h>

#define NMAX 100000
#define EMAX 1600000
#define H 64
#define ED 32
#define NH 4
#define TOPK 10
#define MAXD 96
#define KK 10

// scratch (static device globals -- zero-initialized at module load)
__device__ float g_hW[NMAX * H];       // 25.6 MB
__device__ float g_s1[NMAX * NH];
__device__ float g_s2[NMAX * NH];
__device__ float g_score[EMAX];
__device__ int   g_deg[NMAX];          // invariant: all-zero at entry of each kernel_launch
__device__ int   g_start[NMAX];
__device__ int   g_cursor[NMAX];
__device__ int   g_csr[EMAX];
__device__ int   g_bsum[64];

__global__ void k_count(const int* __restrict__ col, int e_cnt) {
    int i = blockIdx.x * blockDim.x + threadIdx.x;
    if (i < e_cnt) atomicAdd(&g_deg[col[i]], 1);
}

// ---------------------------------------------------------------------------
// multi-block scan of g_deg -> g_start. 2048 elems / block, totals in g_bsum.
// ---------------------------------------------------------------------------
__global__ void __launch_bounds__(256)
k_scan_part(int n) {
    __shared__ int s_wsum[8];
    int b = blockIdx.x, t = threadIdx.x;
    int base = b * 2048 + t * 8;
    int v[8];
    #pragma unroll
    for (int j = 0; j < 8; j++) v[j] = (base + j < n) ? g_deg[base + j] : 0;
    int tsum = 0;
    #pragma unroll
    for (int j = 0; j < 8; j++) { int x = v[j]; v[j] = tsum; tsum += x; }
    int lane = t & 31, wid = t >> 5;
    int x = tsum;
    #pragma unroll
    for (int off = 1; off < 32; off <<= 1) {
        int y = __shfl_up_sync(0xffffffffu, x, off);
        if (lane >= off) x += y;
    }
    if (lane == 31) s_wsum[wid] = x;
    __syncthreads();
    if (t == 0) {
        int a = 0;
        #pragma unroll
        for (int w = 0; w < 8; w++) { int tt = s_wsum[w]; s_wsum[w] = a; a += tt; }
        g_bsum[b] = a;
    }
    __syncthreads();
    int excl = s_wsum[wid] + (x - tsum);
    #pragma unroll
    for (int j = 0; j < 8; j++)
        if (base + j < n) g_start[base + j] = excl + v[j];
}

// scan_add with fused top-level prefix (each block prefixes g_bsum locally)
__global__ void __launch_bounds__(256)
k_scan_add(int n, int nb) {
    __shared__ int s_pref[64];
    int t = threadIdx.x;
    if (t == 0) {
        int a = 0;
        for (int i = 0; i < nb; i++) { int v = g_bsum[i]; s_pref[i] = a; a += v; }
    }
    __syncthreads();
    int i = blockIdx.x * blockDim.x + t;
    if (i < n) {
        int s = g_start[i] + s_pref[i >> 11];
        g_start[i] = s;
        g_cursor[i] = s;
    }
}

// ---------------------------------------------------------------------------
// hW = h @ whW + whb  --  shared-tile register-blocked GEMM.
// Block: 256 threads, tile 64 nodes x 64 cols, each thread a 4x4 block.
// ---------------------------------------------------------------------------
__global__ void __launch_bounds__(256)
k_hw_gemm(const float* __restrict__ h,
          const float* __restrict__ whW,
          const float* __restrict__ whb,
          int n) {
    __shared__ float s_h[64][65];     // padded rows (conflict-free column reads)
    __shared__ float s_w[64 * 64];    // same layout as whW (k-major)
    __shared__ float s_b[64];
    int t = threadIdx.x;
    int base = blockIdx.x * 64;

    // stage W (4096 floats) via float4
    {
        const float4* src = reinterpret_cast<const float4*>(whW);
        float4* dst = reinterpret_cast<float4*>(s_w);
        #pragma unroll
        for (int j = 0; j < 4; j++) dst[t + j * 256] = src[t + j * 256];
    }
    if (t < 64) s_b[t] = whb[t];
    // stage h tile (64 nodes x 64) via float4, zero-pad OOB nodes
    {
        #pragma unroll
        for (int j = 0; j < 4; j++) {
            int idx = t + j * 256;            // float4 index within tile (0..1023)
            int r = idx >> 4;                 // node row 0..63
            int c = (idx & 15) << 2;          // col 0,4,...,60
            float4 v = make_float4(0.f, 0.f, 0.f, 0.f);
            if (base + r < n)
                v = reinterpret_cast<const float4*>(h + (size_t)(base + r) * H + c)[0];
            s_h[r][c]     = v.x;
            s_h[r][c + 1] = v.y;
            s_h[r][c + 2] = v.z;
            s_h[r][c + 3] = v.w;
        }
    }
    __syncthreads();

    int nq = t >> 4;          // node quad 0..15
    int cq = t & 15;          // col quad 0..15
    float acc[4][4];
    #pragma unroll
    for (int i = 0; i < 4; i++)
        #pragma unroll
        for (int j = 0; j < 4; j++) acc[i][j] = 0.f;

    #pragma unroll 8
    for (int k = 0; k < 64; k++) {
        float4 b = *reinterpret_cast<const float4*>(&s_w[k * 64 + cq * 4]);
        float a0 = s_h[nq * 4 + 0][k];
        float a1 = s_h[nq * 4 + 1][k];
        float a2 = s_h[nq * 4 + 2][k];
        float a3 = s_h[nq * 4 + 3][k];
        acc[0][0] += a0 * b.x; acc[0][1] += a0 * b.y; acc[0][2] += a0 * b.z; acc[0][3] += a0 * b.w;
        acc[1][0] += a1 * b.x; acc[1][1] += a1 * b.y; acc[1][2] += a1 * b.z; acc[1][3] += a1 * b.w;
        acc[2][0] += a2 * b.x; acc[2][1] += a2 * b.y; acc[2][2] += a2 * b.z; acc[2][3] += a2 * b.w;
        acc[3][0] += a3 * b.x; acc[3][1] += a3 * b.y; acc[3][2] += a3 * b.z; acc[3][3] += a3 * b.w;
    }

    float4 bias = *reinterpret_cast<const float4*>(&s_b[cq * 4]);
    #pragma unroll
    for (int i = 0; i < 4; i++) {
        int node = base + nq * 4 + i;
        if (node < n) {
            float4 v = make_float4(acc[i][0] + bias.x, acc[i][1] + bias.y,
                                   acc[i][2] + bias.z, acc[i][3] + bias.w);
            reinterpret_cast<float4*>(g_hW + (size_t)node * H + cq * 4)[0] = v;
        }
    }
}

// ---------------------------------------------------------------------------
// s1/s2 attention projections: 8 threads per node, each one (which, head) dot.
// ---------------------------------------------------------------------------
__global__ void __launch_bounds__(256)
k_s1s2(const float* __restrict__ h,
       const float* __restrict__ attn_w,
       int n) {
    __shared__ float s_aw[2 * H * NH];   // 2 KB
    int t = threadIdx.x;
    for (int i = t; i < 2 * H * NH; i += blockDim.x) s_aw[i] = attn_w[i];
    __syncthreads();
    int idx = blockIdx.x * blockDim.x + t;
    int node = idx >> 3;
    if (node >= n) return;
    int sub = idx & 7;
    int which = sub >> 2, head = sub & 3;
    const float* hp = h + (size_t)node * H;
    const float* aw = s_aw + which * H * NH;
    float s = 0.f;
    #pragma unroll
    for (int k = 0; k < H; k++) s += hp[k] * aw[k * NH + head];
    if (which == 0) g_s1[node * NH + head] = s;
    else            g_s2[node * NH + head] = s;
}

// ---------------------------------------------------------------------------
// fused per-edge attention score + CSR scatter.
// ---------------------------------------------------------------------------
__global__ void __launch_bounds__(256)
k_score_scatter(const int* __restrict__ row,
                const int* __restrict__ col,
                const float* __restrict__ edge_attr,
                const float* __restrict__ attn_w,
                int e_cnt) {
    __shared__ float s_a3[ED * NH];
    int tid = threadIdx.x;
    for (int i = tid; i < ED * NH; i += blockDim.x)
        s_a3[i] = attn_w[2 * H * NH + i];
    __syncthreads();

    int e = blockIdx.x * blockDim.x + tid;
    if (e >= e_cnt) return;
    int r = row[e], c = col[e];
    float4 p1 = reinterpret_cast<const float4*>(g_s1)[r];
    float4 p2 = reinterpret_cast<const float4*>(g_s2)[c];
    const float4* ea4 = reinterpret_cast<const float4*>(edge_attr + (size_t)e * ED);
    float s3[NH] = {0.f, 0.f, 0.f, 0.f};
    #pragma unroll
    for (int q = 0; q < 8; q++) {
        float4 v = ea4[q];
        int k = q * 4;
        #pragma unroll
        for (int hd = 0; hd < NH; hd++) {
            s3[hd] += v.x * s_a3[(k    ) * NH + hd];
            s3[hd] += v.y * s_a3[(k + 1) * NH + hd];
            s3[hd] += v.z * s_a3[(k + 2) * NH + hd];
            s3[hd] += v.w * s_a3[(k + 3) * NH + hd];
        }
    }
    float t0 = p1.x + p2.x + s3[0];
    float t1 = p1.y + p2.y + s3[1];
    float t2 = p1.z + p2.z + s3[2];
    float t3 = p1.w + p2.w + s3[3];
    t0 = (t0 >= 0.f) ? t0 : 0.2f * t0;
    t1 = (t1 >= 0.f) ? t1 : 0.2f * t1;
    t2 = (t2 >= 0.f) ? t2 : 0.2f * t2;
    t3 = (t3 >= 0.f) ? t3 : 0.2f * t3;
    g_score[e] = 0.25f * (t0 + t1 + t2 + t3);
    int p = atomicAdd(&g_cursor[c], 1);
    g_csr[p] = e;
}

// ---------------------------------------------------------------------------
// warp-per-node aggregation (no sort; keep-mask order-independent).
//  d<=32 : register path.  32<d<=96 : shared path.  d>96 : global fallback.
// Self-cleaning: zeroes g_deg[node] after use.
// ---------------------------------------------------------------------------
__global__ void __launch_bounds__(256)
k_node_agg(const int* __restrict__ row,
           const float* __restrict__ edge_attr,
           const int* __restrict__ labels,
           const float* __restrict__ weW,
           const float* __restrict__ web,
           float* __restrict__ out,
           int n) {
    __shared__ float s_sc[8][MAXD];
    __shared__ int   s_eid[8][MAXD];
    __shared__ float s_ka[8][KK];
    __shared__ int   s_ke[8][KK];
    __shared__ float s_eav[8][KK][32];
    __shared__ float s_hw[8][KK][64];

    int tid = threadIdx.x;
    int lane = tid & 31, wl = tid >> 5;

    float wlo[ED], whi[ED];
    #pragma unroll
    for (int k = 0; k < ED; k++) {
        wlo[k] = weW[k * H + lane];
        whi[k] = weW[k * H + 32 + lane];
    }
    float blo = web[lane], bhi = web[32 + lane];

    int warpG = (blockIdx.x * blockDim.x + tid) >> 5;
    int nwarps = (gridDim.x * blockDim.x) >> 5;

    for (int node = warpG; node < n; node += nwarps) {
        int d = g_deg[node], st = g_start[node];
        float acc0 = 0.f, acc1 = 0.f, acc2 = 0.f, acc3 = 0.f, acc4 = 0.f, acc5 = 0.f;
        int kk = 0;
        if (d > 0 && d <= 32) {
            // -------- register fast path --------
            bool valid = lane < d;
            int   e  = valid ? g_csr[st + lane] : 0x7FFFFFFF;
            float sc = valid ? g_score[e] : -1e30f;
            float mx = sc;
            #pragma unroll
            for (int off = 16; off; off >>= 1)
                mx = fmaxf(mx, __shfl_xor_sync(0xffffffffu, mx, off));
            float ex = valid ? expf(sc - mx) : 0.f;
            float sum = ex;
            #pragma unroll
            for (int off = 16; off; off >>= 1)
                sum += __shfl_xor_sync(0xffffffffu, sum, off);
            float invden = 1.f / sum;
            int cnt = 0;
            if (d > TOPK) {
                for (int j = 0; j < d; j++) {
                    float scj = __shfl_sync(0xffffffffu, sc, j);
                    int   ej  = __shfl_sync(0xffffffffu, e,  j);
                    cnt += (scj > sc) || (scj == sc && ej < e);
                }
            }
            bool keep = valid && (cnt < TOPK);
            unsigned bal = __ballot_sync(0xffffffffu, keep);
            kk = __popc(bal);
            int pos = __popc(bal & ((1u << lane) - 1u));
            if (keep) {
                s_ka[wl][pos] = ex * invden;
                s_ke[wl][pos] = e;
            }
            __syncwarp();
        } else if (d > 32 && d <= MAXD) {
            // -------- shared path (rare) --------
            for (int i = lane; i < d; i += 32) {
                int e = g_csr[st + i];
                s_eid[wl][i] = e;
                s_sc[wl][i] = g_score[e];
            }
            __syncwarp();
            float mx = -1e30f;
            for (int i = lane; i < d; i += 32) mx = fmaxf(mx, s_sc[wl][i]);
            #pragma unroll
            for (int off = 16; off; off >>= 1)
                mx = fmaxf(mx, __shfl_xor_sync(0xffffffffu, mx, off));
            float sum = 0.f;
            for (int i = lane; i < d; i += 32) sum += expf(s_sc[wl][i] - mx);
            #pragma unroll
            for (int off = 16; off; off >>= 1)
                sum += __shfl_xor_sync(0xffffffffu, sum, off);
            float invden = 1.f / sum;
            for (int base = 0; base < d; base += 32) {
                int i = base + lane;
                bool valid = (i < d);
                bool keep = false;
                float a = 0.f;
                if (valid) {
                    float sci = s_sc[wl][i];
                    int ei = s_eid[wl][i];
                    int c = 0;
                    for (int j = 0; j < d; j++) {
                        float scj = s_sc[wl][j];
                        c += (scj > sci) || (scj == sci && s_eid[wl][j] < ei);
                    }
                    keep = (c < TOPK);
                    if (keep) a = expf(sci - mx) * invden;
                }
                unsigned bal = __ballot_sync(0xffffffffu, valid && keep);
                int pos = kk + __popc(bal & ((1u << lane) - 1u));
                if (valid && keep) {
                    s_ka[wl][pos] = a;
                    s_ke[wl][pos] = s_eid[wl][i];
                }
                kk += __popc(bal);
            }
            __syncwarp();
        } else if (d > MAXD) {
            // -------- giant fallback (effectively never) --------
            int lc = labels[node];
            float mx = -1e30f;
            for (int i = lane; i < d; i += 32) mx = fmaxf(mx, g_score[g_csr[st + i]]);
            #pragma unroll
            for (int off = 16; off; off >>= 1)
                mx = fmaxf(mx, __shfl_xor_sync(0xffffffffu, mx, off));
            float sum = 0.f;
            for (int i = lane; i < d; i += 32) sum += expf(g_score[g_csr[st + i]] - mx);
            #pragma unroll
            for (int off = 16; off; off >>= 1)
                sum += __shfl_xor_sync(0xffffffffu, sum, off);
            float invden = 1.f / sum;
            for (int i = 0; i < d; i++) {
                int e = g_csr[st + i];
                float sci = g_score[e];
                int c = 0;
                for (int j = lane; j < d; j += 32) {
                    int ej = g_csr[st + j];
                    float scj = g_score[ej];
                    c += (scj > sci) || (scj == sci && ej < e);
                }
                #pragma unroll
                for (int off = 16; off; off >>= 1)
                    c += __shfl_xor_sync(0xffffffffu, c, off);
                if (c >= TOPK) continue;
                float a = expf(sci - mx) * invden;
                int r = row[e];
                int lr = labels[r];
                int g = (lr < 0 || lc < 0) ? 2 : ((lr == lc) ? 0 : 1);
                float eav = edge_attr[(size_t)e * ED + lane];
                float v0 = g_hW[(size_t)r * H + lane];
                float v1 = g_hW[(size_t)r * H + 32 + lane];
                float w0 = 0.f, w1 = 0.f;
                #pragma unroll
                for (int k = 0; k < ED; k++) {
                    float b = __shfl_sync(0xffffffffu, eav, k);
                    w0 += b * wlo[k];
                    w1 += b * whi[k];
                }
                float m0 = fmaxf(v0 + w0 + blo, 0.f);
                float m1 = fmaxf(v1 + w1 + bhi, 0.f);
                if (g == 0)      { acc0 += a * m0; acc1 += a * m1; }
                else if (g == 1) { acc2 += a * m0; acc3 += a * m1; }
                else             { acc4 += a * m0; acc5 += a * m1; }
            }
        }

        if (kk > 0) {
            int lc = labels[node];
            int e_reg = 0, r_reg = 0, g_reg = 2;
            float a_reg = 0.f;
            if (lane < kk) {
                e_reg = s_ke[wl][lane];
                a_reg = s_ka[wl][lane];
                r_reg = row[e_reg];
                int lr = labels[r_reg];
                g_reg = (lr < 0 || lc < 0) ? 2 : ((lr == lc) ? 0 : 1);
            }
            // batch prefetch (independent loads -> high MLP)
            for (int i = 0; i < kk; i++) {
                int e_i = __shfl_sync(0xffffffffu, e_reg, i);
                int r_i = __shfl_sync(0xffffffffu, r_reg, i);
                s_eav[wl][i][lane]     = edge_attr[(size_t)e_i * ED + lane];
                s_hw[wl][i][lane]      = g_hW[(size_t)r_i * H + lane];
                s_hw[wl][i][32 + lane] = g_hW[(size_t)r_i * H + 32 + lane];
            }
            __syncwarp();
            // MAC loop: broadcast LDS + FFMA
            for (int i = 0; i < kk; i++) {
                float a = __shfl_sync(0xffffffffu, a_reg, i);
                int g = __shfl_sync(0xffffffffu, g_reg, i);
                float w0 = 0.f, w1 = 0.f;
                #pragma unroll
                for (int k = 0; k < ED; k++) {
                    float bv = s_eav[wl][i][k];
                    w0 += bv * wlo[k];
                    w1 += bv * whi[k];
                }
                float m0 = fmaxf(s_hw[wl][i][lane] + w0 + blo, 0.f);
                float m1 = fmaxf(s_hw[wl][i][32 + lane] + w1 + bhi, 0.f);
                if (g == 0)      { acc0 += a * m0; acc1 += a * m1; }
                else if (g == 1) { acc2 += a * m0; acc3 += a * m1; }
                else             { acc4 += a * m0; acc5 += a * m1; }
            }
        }

        // self-clean for next graph replay (module-load state is all-zero)
        g_deg[node] = 0;

        size_t ob = (size_t)node * (3 * H);
        out[ob + lane]              = acc0;
        out[ob + 32 + lane]         = acc1;
        out[ob + H + lane]          = acc2;
        out[ob + H + 32 + lane]     = acc3;
        out[ob + 2 * H + lane]      = acc4;
        out[ob + 2 * H + 32 + lane] = acc5;
    }
}

// ---------------------------------------------------------------------------
extern "C" void kernel_launch(void* const* d_in, const int* in_sizes, int n_in,
                              void* d_out, int out_size) {
    const float* h         = (const float*)d_in[0];
    const int*   edge_idx  = (const int*)  d_in[1];
    const float* edge_attr = (const float*)d_in[2];
    const int*   labels    = (const int*)  d_in[3];
    const float* attn_w    = (const float*)d_in[4];
    const float* whW       = (const float*)d_in[5];
    const float* whb       = (const float*)d_in[6];
    const float* weW       = (const float*)d_in[7];
    const float* web       = (const float*)d_in[8];
    float* out = (float*)d_out;

    int n = in_sizes[0] / H;
    int e = in_sizes[1] / 2;
    const int* row = edge_idx;
    const int* col = edge_idx + e;

    int nb = (n + 2047) / 2048;

    k_count<<<(e + 255) / 256, 256>>>(col, e);
    k_scan_part<<<nb, 256>>>(n);
    k_scan_add<<<(n + 255) / 256, 256>>>(n, nb);
    k_hw_gemm<<<(n + 63) / 64, 256>>>(h, whW, whb, n);      // profiled slot 4
    k_s1s2<<<(n * 8 + 255) / 256, 256>>>(h, attn_w, n);
    k_score_scatter<<<(e + 255) / 256, 256>>>(row, col, edge_attr, attn_w, e);
    k_node_agg<<<592, 256>>>(row, edge_attr, labels, weW, web, out, n);
}

// round 8
// speedup vs baseline: 1.3448x; 1.0825x over previous
#include <cuda_runtime.h>
#include <math.h>

#define NMAX 100000
#define EMAX 1600000
#define H 64
#define ED 32
#define NH 4
#define TOPK 10
#define MAXD 96
#define KK 10

// scratch (static device globals -- zero-initialized at module load)
__device__ float g_hW[NMAX * H];       // 25.6 MB
__device__ float g_s1[NMAX * NH];
__device__ float g_s2[NMAX * NH];
__device__ int   g_deg[NMAX];          // invariant: all-zero at entry of each kernel_launch
__device__ int   g_start[NMAX];
__device__ int   g_cursor[NMAX];
__device__ int   g_csr[EMAX];          // edge id, CSR order
__device__ float g_cscore[EMAX];       // score, CSR order
__device__ int   g_crow[EMAX];         // row | ((label+1)<<20), CSR order
__device__ int   g_bsum[64];

__global__ void k_count(const int* __restrict__ col, int e_cnt) {
    int i = blockIdx.x * blockDim.x + threadIdx.x;
    if (i < e_cnt) atomicAdd(&g_deg[col[i]], 1);
}

// ---------------------------------------------------------------------------
// multi-block scan of g_deg -> g_start. 2048 elems / block, totals in g_bsum.
// ---------------------------------------------------------------------------
__global__ void __launch_bounds__(256)
k_scan_part(int n) {
    __shared__ int s_wsum[8];
    int b = blockIdx.x, t = threadIdx.x;
    int base = b * 2048 + t * 8;
    int v[8];
    #pragma unroll
    for (int j = 0; j < 8; j++) v[j] = (base + j < n) ? g_deg[base + j] : 0;
    int tsum = 0;
    #pragma unroll
    for (int j = 0; j < 8; j++) { int x = v[j]; v[j] = tsum; tsum += x; }
    int lane = t & 31, wid = t >> 5;
    int x = tsum;
    #pragma unroll
    for (int off = 1; off < 32; off <<= 1) {
        int y = __shfl_up_sync(0xffffffffu, x, off);
        if (lane >= off) x += y;
    }
    if (lane == 31) s_wsum[wid] = x;
    __syncthreads();
    if (t == 0) {
        int a = 0;
        #pragma unroll
        for (int w = 0; w < 8; w++) { int tt = s_wsum[w]; s_wsum[w] = a; a += tt; }
        g_bsum[b] = a;
    }
    __syncthreads();
    int excl = s_wsum[wid] + (x - tsum);
    #pragma unroll
    for (int j = 0; j < 8; j++)
        if (base + j < n) g_start[base + j] = excl + v[j];
}

// scan_add with fused top-level prefix (each block prefixes g_bsum locally)
__global__ void __launch_bounds__(256)
k_scan_add(int n, int nb) {
    __shared__ int s_pref[64];
    int t = threadIdx.x;
    if (t == 0) {
        int a = 0;
        for (int i = 0; i < nb; i++) { int v = g_bsum[i]; s_pref[i] = a; a += v; }
    }
    __syncthreads();
    int i = blockIdx.x * blockDim.x + t;
    if (i < n) {
        int s = g_start[i] + s_pref[i >> 11];
        g_start[i] = s;
        g_cursor[i] = s;
    }
}

// ---------------------------------------------------------------------------
// hW = h @ whW + whb (shared-tile GEMM, 64x64 tile, 4x4 per thread)
// FUSED: s1/s2 attn projections computed from the same h tile.
// ---------------------------------------------------------------------------
__global__ void __launch_bounds__(256)
k_hw_gemm(const float* __restrict__ h,
          const float* __restrict__ whW,
          const float* __restrict__ whb,
          const float* __restrict__ attn_w,
          int n) {
    __shared__ float s_h[64][65];     // padded rows
    __shared__ float s_w[64 * 64];
    __shared__ float s_b[64];
    __shared__ float s_aw[2 * H * NH]; // 2 KB
    int t = threadIdx.x;
    int base = blockIdx.x * 64;

    {
        const float4* src = reinterpret_cast<const float4*>(whW);
        float4* dst = reinterpret_cast<float4*>(s_w);
        #pragma unroll
        for (int j = 0; j < 4; j++) dst[t + j * 256] = src[t + j * 256];
    }
    if (t < 64) s_b[t] = whb[t];
    {
        const float2* src = reinterpret_cast<const float2*>(attn_w);
        float2* dst = reinterpret_cast<float2*>(s_aw);
        dst[t] = src[t];  // 256 float2 = 512 floats
    }
    {
        #pragma unroll
        for (int j = 0; j < 4; j++) {
            int idx = t + j * 256;
            int r = idx >> 4;
            int c = (idx & 15) << 2;
            float4 v = make_float4(0.f, 0.f, 0.f, 0.f);
            if (base + r < n)
                v = reinterpret_cast<const float4*>(h + (size_t)(base + r) * H + c)[0];
            s_h[r][c]     = v.x;
            s_h[r][c + 1] = v.y;
            s_h[r][c + 2] = v.z;
            s_h[r][c + 3] = v.w;
        }
    }
    __syncthreads();

    int nq = t >> 4;
    int cq = t & 15;
    float acc[4][4];
    #pragma unroll
    for (int i = 0; i < 4; i++)
        #pragma unroll
        for (int j = 0; j < 4; j++) acc[i][j] = 0.f;

    #pragma unroll 8
    for (int k = 0; k < 64; k++) {
        float4 b = *reinterpret_cast<const float4*>(&s_w[k * 64 + cq * 4]);
        float a0 = s_h[nq * 4 + 0][k];
        float a1 = s_h[nq * 4 + 1][k];
        float a2 = s_h[nq * 4 + 2][k];
        float a3 = s_h[nq * 4 + 3][k];
        acc[0][0] += a0 * b.x; acc[0][1] += a0 * b.y; acc[0][2] += a0 * b.z; acc[0][3] += a0 * b.w;
        acc[1][0] += a1 * b.x; acc[1][1] += a1 * b.y; acc[1][2] += a1 * b.z; acc[1][3] += a1 * b.w;
        acc[2][0] += a2 * b.x; acc[2][1] += a2 * b.y; acc[2][2] += a2 * b.z; acc[2][3] += a2 * b.w;
        acc[3][0] += a3 * b.x; acc[3][1] += a3 * b.y; acc[3][2] += a3 * b.z; acc[3][3] += a3 * b.w;
    }

    float4 bias = *reinterpret_cast<const float4*>(&s_b[cq * 4]);
    #pragma unroll
    for (int i = 0; i < 4; i++) {
        int node = base + nq * 4 + i;
        if (node < n) {
            float4 v = make_float4(acc[i][0] + bias.x, acc[i][1] + bias.y,
                                   acc[i][2] + bias.z, acc[i][3] + bias.w);
            reinterpret_cast<float4*>(g_hW + (size_t)node * H + cq * 4)[0] = v;
        }
    }

    // fused s1/s2: one (which, head) dot per thread; broadcast rows of s_h.
    {
        int nl = t >> 3;           // node within tile 0..31? no: 256/8 = 32 -> two passes
        int sub = t & 7;
        int which = sub >> 2, head = sub & 3;
        const float* aw = s_aw + which * H * NH + head;
        #pragma unroll
        for (int pass = 0; pass < 2; pass++) {
            int r = nl + pass * 32;
            int node = base + r;
            float s = 0.f;
            #pragma unroll
            for (int k = 0; k < H; k++) s += s_h[r][k] * aw[k * NH];
            if (node < n) {
                if (which == 0) g_s1[node * NH + head] = s;
                else            g_s2[node * NH + head] = s;
            }
        }
    }
}

// ---------------------------------------------------------------------------
// fused per-edge attention score + CSR scatter with payloads (score, row+label).
// ---------------------------------------------------------------------------
__global__ void __launch_bounds__(256)
k_score_scatter(const int* __restrict__ row,
                const int* __restrict__ col,
                const float* __restrict__ edge_attr,
                const float* __restrict__ attn_w,
                const int* __restrict__ labels,
                int e_cnt) {
    __shared__ float s_a3[ED * NH];
    int tid = threadIdx.x;
    for (int i = tid; i < ED * NH; i += blockDim.x)
        s_a3[i] = attn_w[2 * H * NH + i];
    __syncthreads();

    int e = blockIdx.x * blockDim.x + tid;
    if (e >= e_cnt) return;
    int r = row[e], c = col[e];
    int lr = labels[r];
    float4 p1 = reinterpret_cast<const float4*>(g_s1)[r];
    float4 p2 = reinterpret_cast<const float4*>(g_s2)[c];
    const float4* ea4 = reinterpret_cast<const float4*>(edge_attr + (size_t)e * ED);
    float s3[NH] = {0.f, 0.f, 0.f, 0.f};
    #pragma unroll
    for (int q = 0; q < 8; q++) {
        float4 v = ea4[q];
        int k = q * 4;
        #pragma unroll
        for (int hd = 0; hd < NH; hd++) {
            s3[hd] += v.x * s_a3[(k    ) * NH + hd];
            s3[hd] += v.y * s_a3[(k + 1) * NH + hd];
            s3[hd] += v.z * s_a3[(k + 2) * NH + hd];
            s3[hd] += v.w * s_a3[(k + 3) * NH + hd];
        }
    }
    float t0 = p1.x + p2.x + s3[0];
    float t1 = p1.y + p2.y + s3[1];
    float t2 = p1.z + p2.z + s3[2];
    float t3 = p1.w + p2.w + s3[3];
    t0 = (t0 >= 0.f) ? t0 : 0.2f * t0;
    t1 = (t1 >= 0.f) ? t1 : 0.2f * t1;
    t2 = (t2 >= 0.f) ? t2 : 0.2f * t2;
    t3 = (t3 >= 0.f) ? t3 : 0.2f * t3;
    float score = 0.25f * (t0 + t1 + t2 + t3);
    int p = atomicAdd(&g_cursor[c], 1);
    g_csr[p]    = e;
    g_cscore[p] = score;
    g_crow[p]   = r | ((lr + 1) << 20);
}

// ---------------------------------------------------------------------------
// warp-per-node aggregation. Per-node loads are independent & contiguous
// (csr/cscore/crow). No sort. Self-cleaning g_deg.
// ---------------------------------------------------------------------------
__global__ void __launch_bounds__(256)
k_node_agg(const float* __restrict__ edge_attr,
           const int* __restrict__ labels,
           const float* __restrict__ weW,
           const float* __restrict__ web,
           float* __restrict__ out,
           int n) {
    __shared__ float s_sc[8][MAXD];
    __shared__ int   s_eid[8][MAXD];
    __shared__ float s_ka[8][KK];
    __shared__ int   s_ke[8][KK];
    __shared__ int   s_kr[8][KK];
    __shared__ float s_eav[8][KK][32];
    __shared__ float s_hw[8][KK][64];

    int tid = threadIdx.x;
    int lane = tid & 31, wl = tid >> 5;

    float wlo[ED], whi[ED];
    #pragma unroll
    for (int k = 0; k < ED; k++) {
        wlo[k] = weW[k * H + lane];
        whi[k] = weW[k * H + 32 + lane];
    }
    float blo = web[lane], bhi = web[32 + lane];

    int warpG = (blockIdx.x * blockDim.x + tid) >> 5;
    int nwarps = (gridDim.x * blockDim.x) >> 5;

    for (int node = warpG; node < n; node += nwarps) {
        int d = g_deg[node], st = g_start[node];
        float acc0 = 0.f, acc1 = 0.f, acc2 = 0.f, acc3 = 0.f, acc4 = 0.f, acc5 = 0.f;
        int kk = 0;
        if (d > 0 && d <= 32) {
            // -------- register fast path: 3 independent contiguous loads ----
            bool valid = lane < d;
            int idx = st + (valid ? lane : 0);
            int   e  = g_csr[idx];
            float sc = g_cscore[idx];
            int   rl = g_crow[idx];
            if (!valid) { e = 0x7FFFFFFF; sc = -1e30f; }
            float mx = sc;
            #pragma unroll
            for (int off = 16; off; off >>= 1)
                mx = fmaxf(mx, __shfl_xor_sync(0xffffffffu, mx, off));
            float ex = valid ? expf(sc - mx) : 0.f;
            float sum = ex;
            #pragma unroll
            for (int off = 16; off; off >>= 1)
                sum += __shfl_xor_sync(0xffffffffu, sum, off);
            float invden = 1.f / sum;
            int cnt = 0;
            if (d > TOPK) {
                for (int j = 0; j < d; j++) {
                    float scj = __shfl_sync(0xffffffffu, sc, j);
                    int   ej  = __shfl_sync(0xffffffffu, e,  j);
                    cnt += (scj > sc) || (scj == sc && ej < e);
                }
            }
            bool keep = valid && (cnt < TOPK);
            unsigned bal = __ballot_sync(0xffffffffu, keep);
            kk = __popc(bal);
            int pos = __popc(bal & ((1u << lane) - 1u));
            if (keep) {
                s_ka[wl][pos] = ex * invden;
                s_ke[wl][pos] = e;
                s_kr[wl][pos] = rl;
            }
            __syncwarp();
        } else if (d > 32 && d <= MAXD) {
            // -------- shared path (rare) --------
            for (int i = lane; i < d; i += 32) {
                s_eid[wl][i] = g_csr[st + i];
                s_sc[wl][i]  = g_cscore[st + i];
            }
            __syncwarp();
            float mx = -1e30f;
            for (int i = lane; i < d; i += 32) mx = fmaxf(mx, s_sc[wl][i]);
            #pragma unroll
            for (int off = 16; off; off >>= 1)
                mx = fmaxf(mx, __shfl_xor_sync(0xffffffffu, mx, off));
            float sum = 0.f;
            for (int i = lane; i < d; i += 32) sum += expf(s_sc[wl][i] - mx);
            #pragma unroll
            for (int off = 16; off; off >>= 1)
                sum += __shfl_xor_sync(0xffffffffu, sum, off);
            float invden = 1.f / sum;
            for (int base = 0; base < d; base += 32) {
                int i = base + lane;
                bool valid = (i < d);
                bool keep = false;
                float a = 0.f;
                if (valid) {
                    float sci = s_sc[wl][i];
                    int ei = s_eid[wl][i];
                    int c = 0;
                    for (int j = 0; j < d; j++) {
                        float scj = s_sc[wl][j];
                        c += (scj > sci) || (scj == sci && s_eid[wl][j] < ei);
                    }
                    keep = (c < TOPK);
                    if (keep) a = expf(sci - mx) * invden;
                }
                unsigned bal = __ballot_sync(0xffffffffu, valid && keep);
                int pos = kk + __popc(bal & ((1u << lane) - 1u));
                if (valid && keep) {
                    s_ka[wl][pos] = a;
                    s_ke[wl][pos] = s_eid[wl][i];
                    s_kr[wl][pos] = g_crow[st + i];
                }
                kk += __popc(bal);
            }
            __syncwarp();
        } else if (d > MAXD) {
            // -------- giant fallback (effectively never) --------
            float mx = -1e30f;
            for (int i = lane; i < d; i += 32) mx = fmaxf(mx, g_cscore[st + i]);
            #pragma unroll
            for (int off = 16; off; off >>= 1)
                mx = fmaxf(mx, __shfl_xor_sync(0xffffffffu, mx, off));
            float sum = 0.f;
            for (int i = lane; i < d; i += 32) sum += expf(g_cscore[st + i] - mx);
            #pragma unroll
            for (int off = 16; off; off >>= 1)
                sum += __shfl_xor_sync(0xffffffffu, sum, off);
            float invden = 1.f / sum;
            for (int i = 0; i < d; i++) {
                int e = g_csr[st + i];
                float sci = g_cscore[st + i];
                int c = 0;
                for (int j = lane; j < d; j += 32) {
                    int ej = g_csr[st + j];
                    float scj = g_cscore[st + j];
                    c += (scj > sci) || (scj == sci && ej < e);
                }
                #pragma unroll
                for (int off = 16; off; off >>= 1)
                    c += __shfl_xor_sync(0xffffffffu, c, off);
                if (c >= TOPK) continue;
                float a = expf(sci - mx) * invden;
                int rl = g_crow[st + i];
                int r = rl & 0xFFFFF;
                int lr = (rl >> 20) - 1;
                int lc = labels[node];
                int g = (lr < 0 || lc < 0) ? 2 : ((lr == lc) ? 0 : 1);
                float eav = edge_attr[(size_t)e * ED + lane];
                float v0 = g_hW[(size_t)r * H + lane];
                float v1 = g_hW[(size_t)r * H + 32 + lane];
                float w0 = 0.f, w1 = 0.f;
                #pragma unroll
                for (int k = 0; k < ED; k++) {
                    float b = __shfl_sync(0xffffffffu, eav, k);
                    w0 += b * wlo[k];
                    w1 += b * whi[k];
                }
                float m0 = fmaxf(v0 + w0 + blo, 0.f);
                float m1 = fmaxf(v1 + w1 + bhi, 0.f);
                if (g == 0)      { acc0 += a * m0; acc1 += a * m1; }
                else if (g == 1) { acc2 += a * m0; acc3 += a * m1; }
                else             { acc4 += a * m0; acc5 += a * m1; }
            }
        }

        if (kk > 0) {
            int lc = labels[node];
            int e_reg = 0, r_reg = 0, g_reg = 2;
            float a_reg = 0.f;
            if (lane < kk) {
                e_reg = s_ke[wl][lane];
                a_reg = s_ka[wl][lane];
                int rl = s_kr[wl][lane];
                r_reg = rl & 0xFFFFF;
                int lr = (rl >> 20) - 1;
                g_reg = (lr < 0 || lc < 0) ? 2 : ((lr == lc) ? 0 : 1);
            }
            // batch prefetch (independent loads -> high MLP)
            for (int i = 0; i < kk; i++) {
                int e_i = __shfl_sync(0xffffffffu, e_reg, i);
                int r_i = __shfl_sync(0xffffffffu, r_reg, i);
                s_eav[wl][i][lane]     = edge_attr[(size_t)e_i * ED + lane];
                s_hw[wl][i][lane]      = g_hW[(size_t)r_i * H + lane];
                s_hw[wl][i][32 + lane] = g_hW[(size_t)r_i * H + 32 + lane];
            }
            __syncwarp();
            // MAC loop: broadcast LDS + FFMA
            for (int i = 0; i < kk; i++) {
                float a = __shfl_sync(0xffffffffu, a_reg, i);
                int g = __shfl_sync(0xffffffffu, g_reg, i);
                float w0 = 0.f, w1 = 0.f;
                #pragma unroll
                for (int k = 0; k < ED; k++) {
                    float bv = s_eav[wl][i][k];
                    w0 += bv * wlo[k];
                    w1 += bv * whi[k];
                }
                float m0 = fmaxf(s_hw[wl][i][lane] + w0 + blo, 0.f);
                float m1 = fmaxf(s_hw[wl][i][32 + lane] + w1 + bhi, 0.f);
                if (g == 0)      { acc0 += a * m0; acc1 += a * m1; }
                else if (g == 1) { acc2 += a * m0; acc3 += a * m1; }
                else             { acc4 += a * m0; acc5 += a * m1; }
            }
        }

        // self-clean for next graph replay (module-load state is all-zero)
        g_deg[node] = 0;

        size_t ob = (size_t)node * (3 * H);
        out[ob + lane]              = acc0;
        out[ob + 32 + lane]         = acc1;
        out[ob + H + lane]          = acc2;
        out[ob + H + 32 + lane]     = acc3;
        out[ob + 2 * H + lane]      = acc4;
        out[ob + 2 * H + 32 + lane] = acc5;
    }
}

// ---------------------------------------------------------------------------
extern "C" void kernel_launch(void* const* d_in, const int* in_sizes, int n_in,
                              void* d_out, int out_size) {
    const float* h         = (const float*)d_in[0];
    const int*   edge_idx  = (const int*)  d_in[1];
    const float* edge_attr = (const float*)d_in[2];
    const int*   labels    = (const int*)  d_in[3];
    const float* attn_w    = (const float*)d_in[4];
    const float* whW       = (const float*)d_in[5];
    const float* whb       = (const float*)d_in[6];
    const float* weW       = (const float*)d_in[7];
    const float* web       = (const float*)d_in[8];
    float* out = (float*)d_out;

    int n = in_sizes[0] / H;
    int e = in_sizes[1] / 2;
    const int* row = edge_idx;
    const int* col = edge_idx + e;

    int nb = (n + 2047) / 2048;

    k_count<<<(e + 255) / 256, 256>>>(col, e);
    k_scan_part<<<nb, 256>>>(n);
    k_scan_add<<<(n + 255) / 256, 256>>>(n, nb);
    k_hw_gemm<<<(n + 63) / 64, 256>>>(h, whW, whb, attn_w, n);   // profiled slot
    k_score_scatter<<<(e + 255) / 256, 256>>>(row, col, edge_attr, attn_w, labels, e);
    k_node_agg<<<592, 256>>>(edge_attr, labels, weW, web, out, n);
}

// round 9
// speedup vs baseline: 1.3903x; 1.0339x over previous
#include <cuda_runtime.h>
#include <math.h>

#define NMAX 100000
#define EMAX 1600000
#define H 64
#define ED 32
#define NH 4
#define TOPK 10
#define MAXD 96
#define KK 10

typedef unsigned long long u64;

// scratch (static device globals -- zero-initialized at module load)
__device__ float g_hW[NMAX * H];       // 25.6 MB
__device__ float g_s1[NMAX * NH];
__device__ float g_s2[NMAX * NH];
__device__ int   g_deg[NMAX];          // invariant: all-zero at entry of each kernel_launch
__device__ int   g_start[NMAX];
__device__ int   g_cursor[NMAX];
__device__ int   g_csr[EMAX];          // edge id, CSR order
__device__ float g_cscore[EMAX];       // score, CSR order
__device__ int   g_crow[EMAX];         // row | ((label+1)<<20), CSR order
__device__ u64   g_flags[64];          // lookback flags: (epoch<<32)|aggregate
__device__ unsigned g_epoch;           // bumped once per kernel_launch

// ---------------------------------------------------------------------------
// Launch 1 (fused): hW GEMM + s1/s2 (blocks < nbG) and degree count + epoch
// bump (blocks >= nbG).
// ---------------------------------------------------------------------------
__global__ void __launch_bounds__(256)
k_gemm_count(const float* __restrict__ h,
             const float* __restrict__ whW,
             const float* __restrict__ whb,
             const float* __restrict__ attn_w,
             const int* __restrict__ col,
             int n, int e_cnt, int nbG) {
    __shared__ float s_h[64][65];
    __shared__ float s_w[64 * 64];
    __shared__ float s_b[64];
    __shared__ float s_aw[2 * H * NH];
    int t = threadIdx.x;

    if (blockIdx.x >= nbG) {
        // -------- degree count (+ epoch bump once) --------
        if (blockIdx.x == nbG && t == 0) atomicAdd(&g_epoch, 1u);
        int i = (blockIdx.x - nbG) * 256 + t;
        if (i < e_cnt) atomicAdd(&g_deg[col[i]], 1);
        return;
    }

    // -------- GEMM tile --------
    int base = blockIdx.x * 64;
    {
        const float4* src = reinterpret_cast<const float4*>(whW);
        float4* dst = reinterpret_cast<float4*>(s_w);
        #pragma unroll
        for (int j = 0; j < 4; j++) dst[t + j * 256] = src[t + j * 256];
    }
    if (t < 64) s_b[t] = whb[t];
    {
        const float2* src = reinterpret_cast<const float2*>(attn_w);
        float2* dst = reinterpret_cast<float2*>(s_aw);
        dst[t] = src[t];
    }
    {
        #pragma unroll
        for (int j = 0; j < 4; j++) {
            int idx = t + j * 256;
            int r = idx >> 4;
            int c = (idx & 15) << 2;
            float4 v = make_float4(0.f, 0.f, 0.f, 0.f);
            if (base + r < n)
                v = reinterpret_cast<const float4*>(h + (size_t)(base + r) * H + c)[0];
            s_h[r][c]     = v.x;
            s_h[r][c + 1] = v.y;
            s_h[r][c + 2] = v.z;
            s_h[r][c + 3] = v.w;
        }
    }
    __syncthreads();

    int nq = t >> 4;
    int cq = t & 15;
    float acc[4][4];
    #pragma unroll
    for (int i = 0; i < 4; i++)
        #pragma unroll
        for (int j = 0; j < 4; j++) acc[i][j] = 0.f;

    #pragma unroll 8
    for (int k = 0; k < 64; k++) {
        float4 b = *reinterpret_cast<const float4*>(&s_w[k * 64 + cq * 4]);
        float a0 = s_h[nq * 4 + 0][k];
        float a1 = s_h[nq * 4 + 1][k];
        float a2 = s_h[nq * 4 + 2][k];
        float a3 = s_h[nq * 4 + 3][k];
        acc[0][0] += a0 * b.x; acc[0][1] += a0 * b.y; acc[0][2] += a0 * b.z; acc[0][3] += a0 * b.w;
        acc[1][0] += a1 * b.x; acc[1][1] += a1 * b.y; acc[1][2] += a1 * b.z; acc[1][3] += a1 * b.w;
        acc[2][0] += a2 * b.x; acc[2][1] += a2 * b.y; acc[2][2] += a2 * b.z; acc[2][3] += a2 * b.w;
        acc[3][0] += a3 * b.x; acc[3][1] += a3 * b.y; acc[3][2] += a3 * b.z; acc[3][3] += a3 * b.w;
    }

    float4 bias = *reinterpret_cast<const float4*>(&s_b[cq * 4]);
    #pragma unroll
    for (int i = 0; i < 4; i++) {
        int node = base + nq * 4 + i;
        if (node < n) {
            float4 v = make_float4(acc[i][0] + bias.x, acc[i][1] + bias.y,
                                   acc[i][2] + bias.z, acc[i][3] + bias.w);
            reinterpret_cast<float4*>(g_hW + (size_t)node * H + cq * 4)[0] = v;
        }
    }

    // fused s1/s2
    {
        int nl = t >> 3;
        int sub = t & 7;
        int which = sub >> 2, head = sub & 3;
        const float* aw = s_aw + which * H * NH + head;
        #pragma unroll
        for (int pass = 0; pass < 2; pass++) {
            int r = nl + pass * 32;
            int node = base + r;
            float s = 0.f;
            #pragma unroll
            for (int k = 0; k < H; k++) s += s_h[r][k] * aw[k * NH];
            if (node < n) {
                if (which == 0) g_s1[node * NH + head] = s;
                else            g_s2[node * NH + head] = s;
            }
        }
    }
}

// ---------------------------------------------------------------------------
// Launch 2: single-pass scan with epoch-tagged decoupled lookback.
// 2048 elems/block; 49 blocks all resident -> no forward-progress hazard.
// ---------------------------------------------------------------------------
__global__ void __launch_bounds__(256)
k_scan_onepass(int n) {
    __shared__ int s_wsum[8];
    __shared__ int s_off;
    __shared__ unsigned s_cur;
    int b = blockIdx.x, t = threadIdx.x;
    if (t == 0) { s_off = 0; s_cur = *(volatile unsigned*)&g_epoch; }
    __syncthreads();
    unsigned cur = s_cur;

    int base = b * 2048 + t * 8;
    int v[8];
    #pragma unroll
    for (int j = 0; j < 8; j++) v[j] = (base + j < n) ? g_deg[base + j] : 0;
    int tsum = 0;
    #pragma unroll
    for (int j = 0; j < 8; j++) { int x = v[j]; v[j] = tsum; tsum += x; }
    int lane = t & 31, wid = t >> 5;
    int x = tsum;
    #pragma unroll
    for (int off = 1; off < 32; off <<= 1) {
        int y = __shfl_up_sync(0xffffffffu, x, off);
        if (lane >= off) x += y;
    }
    if (lane == 31) s_wsum[wid] = x;
    __syncthreads();
    if (t == 0) {
        int a = 0;
        #pragma unroll
        for (int w = 0; w < 8; w++) { int tt = s_wsum[w]; s_wsum[w] = a; a += tt; }
        atomicExch(&g_flags[b], ((u64)cur << 32) | (unsigned)a);
    }
    __syncthreads();
    // lookback: thread t polls flag t for t < b, accumulate aggregates
    if (t < b) {
        u64 f;
        do { f = atomicOr(&g_flags[t], 0ULL); } while ((unsigned)(f >> 32) != cur);
        atomicAdd(&s_off, (int)(unsigned)f);
    }
    __syncthreads();
    int blockoff = s_off;
    int excl = blockoff + s_wsum[wid] + (x - tsum);
    #pragma unroll
    for (int j = 0; j < 8; j++)
        if (base + j < n) {
            int s = excl + v[j];
            g_start[base + j]  = s;
            g_cursor[base + j] = s;
        }
}

// ---------------------------------------------------------------------------
// Launch 3: per-edge attention score + CSR scatter with payloads.
// ---------------------------------------------------------------------------
__global__ void __launch_bounds__(256)
k_score_scatter(const int* __restrict__ row,
                const int* __restrict__ col,
                const float* __restrict__ edge_attr,
                const float* __restrict__ attn_w,
                const int* __restrict__ labels,
                int e_cnt) {
    __shared__ float s_a3[ED * NH];
    int tid = threadIdx.x;
    for (int i = tid; i < ED * NH; i += blockDim.x)
        s_a3[i] = attn_w[2 * H * NH + i];
    __syncthreads();

    int e = blockIdx.x * blockDim.x + tid;
    if (e >= e_cnt) return;
    int r = row[e], c = col[e];
    int lr = labels[r];
    float4 p1 = reinterpret_cast<const float4*>(g_s1)[r];
    float4 p2 = reinterpret_cast<const float4*>(g_s2)[c];
    const float4* ea4 = reinterpret_cast<const float4*>(edge_attr + (size_t)e * ED);
    float s3[NH] = {0.f, 0.f, 0.f, 0.f};
    #pragma unroll
    for (int q = 0; q < 8; q++) {
        float4 v = ea4[q];
        int k = q * 4;
        #pragma unroll
        for (int hd = 0; hd < NH; hd++) {
            s3[hd] += v.x * s_a3[(k    ) * NH + hd];
            s3[hd] += v.y * s_a3[(k + 1) * NH + hd];
            s3[hd] += v.z * s_a3[(k + 2) * NH + hd];
            s3[hd] += v.w * s_a3[(k + 3) * NH + hd];
        }
    }
    float t0 = p1.x + p2.x + s3[0];
    float t1 = p1.y + p2.y + s3[1];
    float t2 = p1.z + p2.z + s3[2];
    float t3 = p1.w + p2.w + s3[3];
    t0 = (t0 >= 0.f) ? t0 : 0.2f * t0;
    t1 = (t1 >= 0.f) ? t1 : 0.2f * t1;
    t2 = (t2 >= 0.f) ? t2 : 0.2f * t2;
    t3 = (t3 >= 0.f) ? t3 : 0.2f * t3;
    float score = 0.25f * (t0 + t1 + t2 + t3);
    int p = atomicAdd(&g_cursor[c], 1);
    g_csr[p]    = e;
    g_cscore[p] = score;
    g_crow[p]   = r | ((lr + 1) << 20);
}

// ---------------------------------------------------------------------------
// Launch 4 (PROFILED): warp-per-node aggregation.
// Column mapping (2*lane, 2*lane+1): float2 hW loads, float2 out stores,
// float4 broadcast LDS in MAC. Self-cleaning g_deg.
// ---------------------------------------------------------------------------
__global__ void __launch_bounds__(256)
k_node_agg(const float* __restrict__ edge_attr,
           const int* __restrict__ labels,
           const float* __restrict__ weW,
           const float* __restrict__ web,
           float* __restrict__ out,
           int n) {
    __shared__ float  s_sc[8][MAXD];
    __shared__ int    s_eid[8][MAXD];
    __shared__ float  s_ka[8][KK];
    __shared__ int    s_ke[8][KK];
    __shared__ int    s_kr[8][KK];
    __shared__ float4 s_eav4[8][KK][8];   // 10 KB: edge_attr rows (float4 view)
    __shared__ float2 s_hw2[8][KK][32];   // 20 KB: (col 2l, 2l+1) pairs

    int tid = threadIdx.x;
    int lane = tid & 31, wl = tid >> 5;

    // weights for output columns 2*lane, 2*lane+1 (coalesced float2 loads)
    float wA[ED], wB[ED];
    #pragma unroll
    for (int k = 0; k < ED; k++) {
        float2 w = reinterpret_cast<const float2*>(weW + k * H)[lane];
        wA[k] = w.x; wB[k] = w.y;
    }
    float2 bv = reinterpret_cast<const float2*>(web)[lane];
    float bA = bv.x, bB = bv.y;

    int warpG = (blockIdx.x * blockDim.x + tid) >> 5;
    int nwarps = (gridDim.x * blockDim.x) >> 5;

    for (int node = warpG; node < n; node += nwarps) {
        int d = g_deg[node], st = g_start[node];
        float acc0 = 0.f, acc1 = 0.f, acc2 = 0.f, acc3 = 0.f, acc4 = 0.f, acc5 = 0.f;
        int kk = 0;
        if (d > 0 && d <= 32) {
            // -------- register fast path: 3 independent contiguous loads ----
            bool valid = lane < d;
            int idx = st + (valid ? lane : 0);
            int   e  = g_csr[idx];
            float sc = g_cscore[idx];
            int   rl = g_crow[idx];
            if (!valid) { e = 0x7FFFFFFF; sc = -1e30f; }
            float mx = sc;
            #pragma unroll
            for (int off = 16; off; off >>= 1)
                mx = fmaxf(mx, __shfl_xor_sync(0xffffffffu, mx, off));
            float ex = valid ? expf(sc - mx) : 0.f;
            float sum = ex;
            #pragma unroll
            for (int off = 16; off; off >>= 1)
                sum += __shfl_xor_sync(0xffffffffu, sum, off);
            float invden = 1.f / sum;
            int cnt = 0;
            if (d > TOPK) {
                for (int j = 0; j < d; j++) {
                    float scj = __shfl_sync(0xffffffffu, sc, j);
                    int   ej  = __shfl_sync(0xffffffffu, e,  j);
                    cnt += (scj > sc) || (scj == sc && ej < e);
                }
            }
            bool keep = valid && (cnt < TOPK);
            unsigned bal = __ballot_sync(0xffffffffu, keep);
            kk = __popc(bal);
            int pos = __popc(bal & ((1u << lane) - 1u));
            if (keep) {
                s_ka[wl][pos] = ex * invden;
                s_ke[wl][pos] = e;
                s_kr[wl][pos] = rl;
            }
            __syncwarp();
        } else if (d > 32 && d <= MAXD) {
            // -------- shared path (rare) --------
            for (int i = lane; i < d; i += 32) {
                s_eid[wl][i] = g_csr[st + i];
                s_sc[wl][i]  = g_cscore[st + i];
            }
            __syncwarp();
            float mx = -1e30f;
            for (int i = lane; i < d; i += 32) mx = fmaxf(mx, s_sc[wl][i]);
            #pragma unroll
            for (int off = 16; off; off >>= 1)
                mx = fmaxf(mx, __shfl_xor_sync(0xffffffffu, mx, off));
            float sum = 0.f;
            for (int i = lane; i < d; i += 32) sum += expf(s_sc[wl][i] - mx);
            #pragma unroll
            for (int off = 16; off; off >>= 1)
                sum += __shfl_xor_sync(0xffffffffu, sum, off);
            float invden = 1.f / sum;
            for (int base = 0; base < d; base += 32) {
                int i = base + lane;
                bool valid = (i < d);
                bool keep = false;
                float a = 0.f;
                if (valid) {
                    float sci = s_sc[wl][i];
                    int ei = s_eid[wl][i];
                    int c = 0;
                    for (int j = 0; j < d; j++) {
                        float scj = s_sc[wl][j];
                        c += (scj > sci) || (scj == sci && s_eid[wl][j] < ei);
                    }
                    keep = (c < TOPK);
                    if (keep) a = expf(sci - mx) * invden;
                }
                unsigned bal = __ballot_sync(0xffffffffu, valid && keep);
                int pos = kk + __popc(bal & ((1u << lane) - 1u));
                if (valid && keep) {
                    s_ka[wl][pos] = a;
                    s_ke[wl][pos] = s_eid[wl][i];
                    s_kr[wl][pos] = g_crow[st + i];
                }
                kk += __popc(bal);
            }
            __syncwarp();
        } else if (d > MAXD) {
            // -------- giant fallback (effectively never) --------
            float mx = -1e30f;
            for (int i = lane; i < d; i += 32) mx = fmaxf(mx, g_cscore[st + i]);
            #pragma unroll
            for (int off = 16; off; off >>= 1)
                mx = fmaxf(mx, __shfl_xor_sync(0xffffffffu, mx, off));
            float sum = 0.f;
            for (int i = lane; i < d; i += 32) sum += expf(g_cscore[st + i] - mx);
            #pragma unroll
            for (int off = 16; off; off >>= 1)
                sum += __shfl_xor_sync(0xffffffffu, sum, off);
            float invden = 1.f / sum;
            for (int i = 0; i < d; i++) {
                int e = g_csr[st + i];
                float sci = g_cscore[st + i];
                int c = 0;
                for (int j = lane; j < d; j += 32) {
                    int ej = g_csr[st + j];
                    float scj = g_cscore[st + j];
                    c += (scj > sci) || (scj == sci && ej < e);
                }
                #pragma unroll
                for (int off = 16; off; off >>= 1)
                    c += __shfl_xor_sync(0xffffffffu, c, off);
                if (c >= TOPK) continue;
                float a = expf(sci - mx) * invden;
                int rl = g_crow[st + i];
                int r = rl & 0xFFFFF;
                int lr = (rl >> 20) - 1;
                int lc = labels[node];
                int g = (lr < 0 || lc < 0) ? 2 : ((lr == lc) ? 0 : 1);
                float eav = edge_attr[(size_t)e * ED + lane];
                float2 hv = reinterpret_cast<const float2*>(g_hW + (size_t)r * H)[lane];
                float w0 = 0.f, w1 = 0.f;
                #pragma unroll
                for (int k = 0; k < ED; k++) {
                    float b = __shfl_sync(0xffffffffu, eav, k);
                    w0 += b * wA[k];
                    w1 += b * wB[k];
                }
                float m0 = fmaxf(hv.x + w0 + bA, 0.f);
                float m1 = fmaxf(hv.y + w1 + bB, 0.f);
                if (g == 0)      { acc0 += a * m0; acc1 += a * m1; }
                else if (g == 1) { acc2 += a * m0; acc3 += a * m1; }
                else             { acc4 += a * m0; acc5 += a * m1; }
            }
        }

        if (kk > 0) {
            int lc = labels[node];
            int e_reg = 0, r_reg = 0, g_reg = 2;
            float a_reg = 0.f;
            if (lane < kk) {
                e_reg = s_ke[wl][lane];
                a_reg = s_ka[wl][lane];
                int rl = s_kr[wl][lane];
                r_reg = rl & 0xFFFFF;
                int lr = (rl >> 20) - 1;
                g_reg = (lr < 0 || lc < 0) ? 2 : ((lr == lc) ? 0 : 1);
            }
            // batch prefetch (independent loads -> high MLP)
            for (int i = 0; i < kk; i++) {
                int e_i = __shfl_sync(0xffffffffu, e_reg, i);
                int r_i = __shfl_sync(0xffffffffu, r_reg, i);
                reinterpret_cast<float*>(&s_eav4[wl][i][0])[lane] =
                    edge_attr[(size_t)e_i * ED + lane];
                s_hw2[wl][i][lane] =
                    reinterpret_cast<const float2*>(g_hW + (size_t)r_i * H)[lane];
            }
            __syncwarp();
            // MAC loop: float4 broadcast LDS + FFMA
            for (int i = 0; i < kk; i++) {
                float a = __shfl_sync(0xffffffffu, a_reg, i);
                int g = __shfl_sync(0xffffffffu, g_reg, i);
                float m0 = bA, m1 = bB;
                #pragma unroll
                for (int k4 = 0; k4 < 8; k4++) {
                    float4 v = s_eav4[wl][i][k4];
                    int k = k4 * 4;
                    m0 += v.x * wA[k];     m1 += v.x * wB[k];
                    m0 += v.y * wA[k + 1]; m1 += v.y * wB[k + 1];
                    m0 += v.z * wA[k + 2]; m1 += v.z * wB[k + 2];
                    m0 += v.w * wA[k + 3]; m1 += v.w * wB[k + 3];
                }
                float2 hv = s_hw2[wl][i][lane];
                m0 = fmaxf(m0 + hv.x, 0.f);
                m1 = fmaxf(m1 + hv.y, 0.f);
                if (g == 0)      { acc0 += a * m0; acc1 += a * m1; }
                else if (g == 1) { acc2 += a * m0; acc3 += a * m1; }
                else             { acc4 += a * m0; acc5 += a * m1; }
            }
        }

        // self-clean for next graph replay
        g_deg[node] = 0;

        // coalesced float2 stores: group g columns (2*lane, 2*lane+1)
        size_t ob = (size_t)node * (3 * H);
        reinterpret_cast<float2*>(out + ob)[lane]           = make_float2(acc0, acc1);
        reinterpret_cast<float2*>(out + ob + H)[lane]       = make_float2(acc2, acc3);
        reinterpret_cast<float2*>(out + ob + 2 * H)[lane]   = make_float2(acc4, acc5);
    }
}

// ---------------------------------------------------------------------------
extern "C" void kernel_launch(void* const* d_in, const int* in_sizes, int n_in,
                              void* d_out, int out_size) {
    const float* h         = (const float*)d_in[0];
    const int*   edge_idx  = (const int*)  d_in[1];
    const float* edge_attr = (const float*)d_in[2];
    const int*   labels    = (const int*)  d_in[3];
    const float* attn_w    = (const float*)d_in[4];
    const float* whW       = (const float*)d_in[5];
    const float* whb       = (const float*)d_in[6];
    const float* weW       = (const float*)d_in[7];
    const float* web       = (const float*)d_in[8];
    float* out = (float*)d_out;

    int n = in_sizes[0] / H;
    int e = in_sizes[1] / 2;
    const int* row = edge_idx;
    const int* col = edge_idx + e;

    int nbG = (n + 63) / 64;
    int nbC = (e + 255) / 256;
    int nbS = (n + 2047) / 2048;   // <= 64

    k_gemm_count<<<nbG + nbC, 256>>>(h, whW, whb, attn_w, col, n, e, nbG);
    k_scan_onepass<<<nbS, 256>>>(n);
    k_score_scatter<<<(e + 255) / 256, 256>>>(row, col, edge_attr, attn_w, labels, e);
    k_node_agg<<<592, 256>>>(edge_attr, labels, weW, web, out, n);  // profiled slot
}